// round 5
// baseline (speedup 1.0000x reference)
#include <cuda_runtime.h>
#include <cstdint>

#define NN 65536
#define NE (NN*16)
#define NG 128
#define PN 512
#define HIDD 128
#define INDIM 64
#define BN_EPS 1e-5f

__device__ __forceinline__ uint32_t f2tf32(float f){
  uint32_t u; asm("cvt.rna.tf32.f32 %0, %1;" : "=r"(u) : "f"(f)); return u;
}
__device__ __forceinline__ void mma_tf32(float& c0, float& c1, float& c2, float& c3,
                                         uint32_t a0, uint32_t a1, uint32_t a2, uint32_t a3,
                                         uint32_t b0, uint32_t b1){
  asm volatile("mma.sync.aligned.m16n8k8.row.col.f32.tf32.tf32.f32 "
               "{%0,%1,%2,%3}, {%4,%5,%6,%7}, {%8,%9}, {%0,%1,%2,%3};"
               : "+f"(c0), "+f"(c1), "+f"(c2), "+f"(c3)
               : "r"(a0), "r"(a1), "r"(a2), "r"(a3), "r"(b0), "r"(b1));
}

// ================= scratch =================
__device__ int   g_count[NN];
__device__ int   g_rowptr[NN+1];
__device__ int   g_cursor[NN];
__device__ int   g_part[256];
__device__ int   g_poff[256];
__device__ int   g_esrc[NE];
__device__ float g_ew[NE];
__device__ float g_dis[NN];
__device__ float g_selfn[NN];
__device__ float g_h[(size_t)NN*HIDD];
__device__ float g_agg[(size_t)NN*HIDD];
__device__ float g_qkv[(size_t)NN*3*HIDD];
__device__ float g_attno[(size_t)NN*HIDD];

// ================= CSR build =================
__global__ void zero_count_kernel(){
  int n = blockIdx.x*blockDim.x + threadIdx.x;
  if(n < NN) g_count[n] = 0;
}
__global__ void count_kernel(const int* __restrict__ dst){
  int e = blockIdx.x*blockDim.x + threadIdx.x;
  if(e < NE) atomicAdd(&g_count[dst[e]], 1);
}
__global__ void deg_kernel(){
  int n = blockIdx.x*blockDim.x + threadIdx.x;
  if(n >= NN) return;
  float dis = rsqrtf((float)(g_count[n] + 1));
  g_dis[n] = dis;
  g_selfn[n] = dis*dis;
}
__global__ void scan1_kernel(){
  __shared__ int wsum[8];
  int b = blockIdx.x, t = threadIdx.x;
  int i = b*256 + t;
  int c = g_count[i];
  int lane = t & 31, w = t >> 5;
  int v = c;
  #pragma unroll
  for(int o=1;o<32;o<<=1){ int u=__shfl_up_sync(0xffffffffu,v,o); if(lane>=o) v+=u; }
  if(lane==31) wsum[w]=v;
  __syncthreads();
  if(w==0){
    int s = (lane<8)? wsum[lane] : 0;
    #pragma unroll
    for(int o=1;o<8;o<<=1){ int u=__shfl_up_sync(0xffffffffu,s,o); if(lane>=o) s+=u; }
    if(lane<8) wsum[lane]=s;
  }
  __syncthreads();
  int excl = v - c + (w ? wsum[w-1] : 0);
  g_rowptr[i] = excl;
  if(t==255) g_part[b] = excl + c;
}
__global__ void scan2_kernel(){
  __shared__ int wsum[8];
  int t = threadIdx.x;
  int v = g_part[t];
  int lane = t & 31, w = t >> 5;
  int s = v;
  #pragma unroll
  for(int o=1;o<32;o<<=1){ int u=__shfl_up_sync(0xffffffffu,s,o); if(lane>=o) s+=u; }
  if(lane==31) wsum[w]=s;
  __syncthreads();
  if(w==0){
    int x = (lane<8)? wsum[lane] : 0;
    #pragma unroll
    for(int o=1;o<8;o<<=1){ int u=__shfl_up_sync(0xffffffffu,x,o); if(lane>=o) x+=u; }
    if(lane<8) wsum[lane]=x;
  }
  __syncthreads();
  g_poff[t] = s - v + (w ? wsum[w-1] : 0);
}
__global__ void scan3_kernel(){
  int b = blockIdx.x, t = threadIdx.x;
  int i = b*256 + t;
  int r = g_rowptr[i] + g_poff[b];
  g_rowptr[i] = r;
  g_cursor[i] = r;
  if(i == 0) g_rowptr[NN] = NE;
}
__global__ void fill_kernel(const int* __restrict__ src, const int* __restrict__ dst){
  int e = blockIdx.x*blockDim.x + threadIdx.x;
  if(e >= NE) return;
  int s = src[e], d = dst[e];
  int pos = atomicAdd(&g_cursor[d], 1);
  g_esrc[pos] = s;
  g_ew[pos] = g_dis[s]*g_dis[d];
}

// ================= aggregation (warp per node, gather-only) =================
__global__ void agg64_kernel(const float* __restrict__ hin, float* __restrict__ out){
  int gw = (blockIdx.x*blockDim.x + threadIdx.x) >> 5;
  int lane = threadIdx.x & 31;
  if(gw >= NN) return;
  float2 a = *((const float2*)(hin + (size_t)gw*INDIM) + lane);
  float sn = g_selfn[gw];
  a.x *= sn; a.y *= sn;
  int beg = g_rowptr[gw], end = g_rowptr[gw+1];
  for(int e = beg; e < end; e++){
    int s = g_esrc[e];
    float w = g_ew[e];
    float2 v = *((const float2*)(hin + (size_t)s*INDIM) + lane);
    a.x += w*v.x; a.y += w*v.y;
  }
  *((float2*)(out + (size_t)gw*INDIM) + lane) = a;
}
__global__ void agg128_kernel(const float* __restrict__ hin, float* __restrict__ out){
  int gw = (blockIdx.x*blockDim.x + threadIdx.x) >> 5;
  int lane = threadIdx.x & 31;
  if(gw >= NN) return;
  float4 a = *((const float4*)(hin + (size_t)gw*HIDD) + lane);
  float sn = g_selfn[gw];
  a.x *= sn; a.y *= sn; a.z *= sn; a.w *= sn;
  int beg = g_rowptr[gw], end = g_rowptr[gw+1];
  for(int e = beg; e < end; e++){
    int s = g_esrc[e];
    float w = g_ew[e];
    float4 v = *((const float4*)(hin + (size_t)s*HIDD) + lane);
    a.x += w*v.x; a.y += w*v.y; a.z += w*v.z; a.w += w*v.w;
  }
  *((float4*)(out + (size_t)gw*HIDD) + lane) = a;
}

// ================= tf32 mma.sync GEMM =================
// C[128 x 128 tile] = A[M,KK] x Bop (+bias, optional BN+ReLU), fp32 accumulate.
// BT=1: B is [Ncols, KK] row-major (x @ W^T).  BT=0: B is [KK, Ndt] (h @ W).
// smem: As[128][KK+4] (tf32 bits), Bs[128][KK+4] with Bs[n][k] = Bmma[k][n].
// Stride (KK+4) = 4 (mod 32) makes all fragment LDS patterns conflict-free.
template<int BT, int EPI, int KK>
__global__ __launch_bounds__(256)
void gemm_mma_kernel(const float* __restrict__ A, const float* __restrict__ B,
                     const float* __restrict__ bias,
                     const float* __restrict__ bng, const float* __restrict__ bnb,
                     const float* __restrict__ bnm, const float* __restrict__ bnv,
                     float* __restrict__ C, int Ndt)
{
  constexpr int SA = KK + 4;
  extern __shared__ uint32_t sm[];
  uint32_t* As = sm;              // [128][SA]
  uint32_t* Bs = sm + 128*SA;     // [128][SA]
  const int tid = threadIdx.x;
  const int lane = tid & 31, wid = tid >> 5;
  const int row0 = blockIdx.x * 128;
  const int col0 = blockIdx.y * 128;

  // stage A (tf32-rounded)
  constexpr int KQ = KK/4;
  for(int idx = tid; idx < 128*KQ; idx += 256){
    int r = idx / KQ, q = idx % KQ;
    float4 v = *(const float4*)(A + (size_t)(row0 + r)*KK + q*4);
    uint32_t* d = As + r*SA + q*4;
    d[0]=f2tf32(v.x); d[1]=f2tf32(v.y); d[2]=f2tf32(v.z); d[3]=f2tf32(v.w);
  }
  // stage B as Bs[n][k]
  if(BT){
    for(int idx = tid; idx < 128*KQ; idx += 256){
      int r = idx / KQ, q = idx % KQ;
      float4 v = *(const float4*)(B + (size_t)(col0 + r)*KK + q*4);
      uint32_t* d = Bs + r*SA + q*4;
      d[0]=f2tf32(v.x); d[1]=f2tf32(v.y); d[2]=f2tf32(v.z); d[3]=f2tf32(v.w);
    }
  } else {
    for(int idx = tid; idx < KK*32; idx += 256){
      int k = idx >> 5, n4 = idx & 31;
      float4 v = *(const float4*)(B + (size_t)k*Ndt + col0 + n4*4);
      Bs[(n4*4+0)*SA + k] = f2tf32(v.x);
      Bs[(n4*4+1)*SA + k] = f2tf32(v.y);
      Bs[(n4*4+2)*SA + k] = f2tf32(v.z);
      Bs[(n4*4+3)*SA + k] = f2tf32(v.w);
    }
  }
  __syncthreads();

  // warp tile: 32 rows x 64 cols. wr = wid>>1 (4 row blocks), wc = wid&1 (2 col blocks).
  const int m0 = (wid >> 1) * 32;
  const int n0 = (wid & 1) * 64;
  const int g  = lane >> 2;     // groupID
  const int t4 = lane & 3;      // thread in group

  float acc[2][8][4];
  #pragma unroll
  for(int i=0;i<2;i++)
    #pragma unroll
    for(int j=0;j<8;j++)
      #pragma unroll
      for(int q=0;q<4;q++) acc[i][j][q]=0.f;

  #pragma unroll
  for(int ks = 0; ks < KK/8; ks++){
    const int k0 = ks*8 + t4;
    uint32_t af[2][4];
    #pragma unroll
    for(int mi = 0; mi < 2; mi++){
      int r = m0 + mi*16 + g;
      af[mi][0] = As[ r     *SA + k0    ];
      af[mi][1] = As[(r + 8)*SA + k0    ];
      af[mi][2] = As[ r     *SA + k0 + 4];
      af[mi][3] = As[(r + 8)*SA + k0 + 4];
    }
    #pragma unroll
    for(int nj = 0; nj < 8; nj++){
      int n = n0 + nj*8 + g;
      uint32_t b0 = Bs[n*SA + k0];
      uint32_t b1 = Bs[n*SA + k0 + 4];
      #pragma unroll
      for(int mi = 0; mi < 2; mi++)
        mma_tf32(acc[mi][nj][0], acc[mi][nj][1], acc[mi][nj][2], acc[mi][nj][3],
                 af[mi][0], af[mi][1], af[mi][2], af[mi][3], b0, b1);
    }
  }

  // epilogue
  #pragma unroll
  for(int mi = 0; mi < 2; mi++){
    #pragma unroll
    for(int nj = 0; nj < 8; nj++){
      int c = col0 + n0 + nj*8 + t4*2;
      float s0, s1;
      if(EPI){
        s0 = bng[c  ]*rsqrtf(bnv[c  ] + BN_EPS);
        s1 = bng[c+1]*rsqrtf(bnv[c+1] + BN_EPS);
      }
      #pragma unroll
      for(int h = 0; h < 2; h++){
        int r = row0 + m0 + mi*16 + g + h*8;
        float v0 = acc[mi][nj][h*2+0] + bias[c];
        float v1 = acc[mi][nj][h*2+1] + bias[c+1];
        if(EPI){
          v0 = fmaxf((v0 - bnm[c  ])*s0 + bnb[c  ], 0.f);
          v1 = fmaxf((v1 - bnm[c+1])*s1 + bnb[c+1], 0.f);
        }
        *(float2*)(C + (size_t)r*Ndt + c) = make_float2(v0, v1);
      }
    }
  }
}

// ================= attention: CTA per (graph, head) =================
// smem: Ks[512][36] | Vs[512][32] | Qs[32][32] | S[32][516]
__global__ __launch_bounds__(256)
void attn_kernel(const float* __restrict__ qkv, float* __restrict__ out){
  extern __shared__ float smf[];
  float* Ks = smf;                  // 512*36
  float* Vs = Ks + 512*36;          // 512*32
  float* Qs = Vs + 512*32;          // 32*32
  float* S  = Qs + 32*32;           // 32*516
  int g  = blockIdx.x >> 2;
  int hd = blockIdx.x & 3;
  int n0 = g*PN;
  int t = threadIdx.x;
  int lane = t & 31, warp = t >> 5;
  const float scale = 0.17677669529663687f;  // 1/sqrt(32)

  for(int idx = t; idx < PN*8; idx += 256){
    int r = idx >> 3, d4 = idx & 7;
    const float* row = qkv + (size_t)(n0 + r)*384 + hd*32;
    *(float4*)(Ks + r*36 + d4*4) = *(const float4*)(row + 128 + d4*4);
    *(float4*)(Vs + r*32 + d4*4) = *(const float4*)(row + 256 + d4*4);
  }
  __syncthreads();

  for(int qt = 0; qt < 16; qt++){
    for(int idx = t; idx < 32*8; idx += 256){
      int r = idx >> 3, d4 = idx & 7;
      *(float4*)(Qs + r*32 + d4*4) =
        *(const float4*)(qkv + (size_t)(n0 + qt*32 + r)*384 + hd*32 + d4*4);
    }
    __syncthreads();

    // Phase A: S = Q K^T * scale
    int r0 = warp*4;
    for(int kb = 0; kb < 4; kb++){
      float acc[4][4] = {};
      const float* kb0 = Ks + (kb*128 + lane)*36;
      #pragma unroll
      for(int d4 = 0; d4 < 8; d4++){
        float4 q[4], kk[4];
        #pragma unroll
        for(int i=0;i<4;i++) q[i]  = *(const float4*)(Qs + (r0+i)*32 + d4*4);
        #pragma unroll
        for(int j=0;j<4;j++) kk[j] = *(const float4*)(kb0 + j*32*36 + d4*4);
        #pragma unroll
        for(int i=0;i<4;i++)
          #pragma unroll
          for(int j=0;j<4;j++)
            acc[i][j] += q[i].x*kk[j].x + q[i].y*kk[j].y + q[i].z*kk[j].z + q[i].w*kk[j].w;
      }
      #pragma unroll
      for(int i=0;i<4;i++)
        #pragma unroll
        for(int j=0;j<4;j++)
          S[(r0+i)*516 + kb*128 + j*32 + lane] = acc[i][j]*scale;
    }
    __syncthreads();

    // Phase B: row softmax
    for(int rr = 0; rr < 4; rr++){
      int r = warp*4 + rr;
      float mx = -1e30f;
      for(int j = lane; j < 512; j += 32) mx = fmaxf(mx, S[r*516 + j]);
      #pragma unroll
      for(int o=16;o;o>>=1) mx = fmaxf(mx, __shfl_xor_sync(0xffffffffu, mx, o));
      float sum = 0.f;
      for(int j = lane; j < 512; j += 32){
        float e = __expf(S[r*516 + j] - mx);
        S[r*516 + j] = e;
        sum += e;
      }
      #pragma unroll
      for(int o=16;o;o>>=1) sum += __shfl_xor_sync(0xffffffffu, sum, o);
      float inv = 1.f/sum;
      for(int j = lane; j < 512; j += 32) S[r*516 + j] *= inv;
    }
    __syncthreads();

    // Phase C: O = P V
    {
      int qi = t >> 3;
      int dbase = (t & 7)*4;
      float o0=0,o1=0,o2=0,o3=0;
      const float* Srow = S + qi*516;
      #pragma unroll 4
      for(int j4 = 0; j4 < 128; j4++){
        float4 p  = *(const float4*)(Srow + j4*4);
        float4 v0 = *(const float4*)(Vs + (j4*4+0)*32 + dbase);
        float4 v1 = *(const float4*)(Vs + (j4*4+1)*32 + dbase);
        float4 v2 = *(const float4*)(Vs + (j4*4+2)*32 + dbase);
        float4 v3 = *(const float4*)(Vs + (j4*4+3)*32 + dbase);
        o0 += p.x*v0.x + p.y*v1.x + p.z*v2.x + p.w*v3.x;
        o1 += p.x*v0.y + p.y*v1.y + p.z*v2.y + p.w*v3.y;
        o2 += p.x*v0.z + p.y*v1.z + p.z*v2.z + p.w*v3.z;
        o3 += p.x*v0.w + p.y*v1.w + p.z*v2.w + p.w*v3.w;
      }
      int n = n0 + qt*32 + qi;
      *(float4*)(out + (size_t)n*HIDD + hd*32 + dbase) = make_float4(o0,o1,o2,o3);
    }
    __syncthreads();
  }
}

// ================= mean pool =================
__global__ void pool_kernel(const float* __restrict__ fin, float* __restrict__ emb){
  int g = blockIdx.x, d = threadIdx.x;
  float s = 0.f;
  const float* base = fin + (size_t)g*PN*HIDD + d;
  for(int i = 0; i < PN; i++) s += base[(size_t)i*HIDD];
  emb[g*HIDD + d] = s * (1.0f/PN);
}

// ================= launch =================
extern "C" void kernel_launch(void* const* d_in, const int* in_sizes, int n_in,
                              void* d_out, int out_size) {
  const float* x   = (const float*)d_in[0];
  const float* W0  = (const float*)d_in[1];
  const float* b0  = (const float*)d_in[2];
  const float* Wh  = (const float*)d_in[3];
  const float* bh  = (const float*)d_in[4];
  const float* bng = (const float*)d_in[5];
  const float* bnb = (const float*)d_in[6];
  const float* bnm = (const float*)d_in[7];
  const float* bnv = (const float*)d_in[8];
  const float* aiw = (const float*)d_in[9];
  const float* aib = (const float*)d_in[10];
  const float* aow = (const float*)d_in[11];
  const float* aob = (const float*)d_in[12];
  const int*  eidx = (const int*)d_in[13];

  float* out_final = (float*)d_out;
  float* out_emb   = out_final + (size_t)NN*HIDD;

  const int* src = eidx;
  const int* dst = eidx + NE;

  float *p_h, *p_agg, *p_qkv, *p_attno;
  cudaGetSymbolAddress((void**)&p_h,     g_h);
  cudaGetSymbolAddress((void**)&p_agg,   g_agg);
  cudaGetSymbolAddress((void**)&p_qkv,   g_qkv);
  cudaGetSymbolAddress((void**)&p_attno, g_attno);

  const int GEMM_SMEM64  = 2*128*68*4;    // 69632
  const int GEMM_SMEM128 = 2*128*132*4;   // 135168
  const int ATTN_SMEM = (512*36 + 512*32 + 32*32 + 32*516)*4;  // 209408
  cudaFuncSetAttribute(gemm_mma_kernel<0,1,64>,  cudaFuncAttributeMaxDynamicSharedMemorySize, GEMM_SMEM64);
  cudaFuncSetAttribute(gemm_mma_kernel<0,1,128>, cudaFuncAttributeMaxDynamicSharedMemorySize, GEMM_SMEM128);
  cudaFuncSetAttribute(gemm_mma_kernel<1,0,128>, cudaFuncAttributeMaxDynamicSharedMemorySize, GEMM_SMEM128);
  cudaFuncSetAttribute(attn_kernel,              cudaFuncAttributeMaxDynamicSharedMemorySize, ATTN_SMEM);

  // CSR build
  zero_count_kernel<<<NN/256, 256>>>();
  count_kernel<<<NE/256, 256>>>(dst);
  deg_kernel<<<NN/256, 256>>>();
  scan1_kernel<<<256, 256>>>();
  scan2_kernel<<<1, 256>>>();
  scan3_kernel<<<256, 256>>>();
  fill_kernel<<<NE/256, 256>>>(src, dst);

  // layer 0: aggregate in input space (64-d), then tf32 GEMM + BN + ReLU
  agg64_kernel<<<NN*32/256, 256>>>(x, p_agg);
  gemm_mma_kernel<0,1,64><<<dim3(512,1), 256, GEMM_SMEM64>>>(
      p_agg, W0, b0, bng, bnb, bnm, bnv, p_h, 128);

  // layers 1..3
  for(int l = 0; l < 3; l++){
    agg128_kernel<<<NN*32/256, 256>>>(p_h, p_agg);
    gemm_mma_kernel<0,1,128><<<dim3(512,1), 256, GEMM_SMEM128>>>(
        p_agg, Wh + (size_t)l*HIDD*HIDD, bh + l*HIDD,
        bng + (l+1)*HIDD, bnb + (l+1)*HIDD, bnm + (l+1)*HIDD, bnv + (l+1)*HIDD,
        p_h, 128);
  }

  // qkv projection: [N,128] @ attn_in_w^T -> [N,384]
  gemm_mma_kernel<1,0,128><<<dim3(512,3), 256, GEMM_SMEM128>>>(
      p_h, aiw, aib, nullptr, nullptr, nullptr, nullptr, p_qkv, 384);

  // attention per (graph, head)
  attn_kernel<<<NG*4, 256, ATTN_SMEM>>>(p_qkv, p_attno);

  // output projection -> final
  gemm_mma_kernel<1,0,128><<<dim3(512,1), 256, GEMM_SMEM128>>>(
      p_attno, aow, aob, nullptr, nullptr, nullptr, nullptr, out_final, 128);

  // mean pool -> graph_emb
  pool_kernel<<<NG, HIDD>>>(out_final, out_emb);
}

// round 6
// speedup vs baseline: 1.6387x; 1.6387x over previous
#include <cuda_runtime.h>
#include <cstdint>

#define NN 65536
#define NE (NN*16)
#define NG 128
#define PN 512
#define HIDD 128
#define INDIM 64
#define BN_EPS 1e-5f

__device__ __forceinline__ uint32_t f2tf32(float f){
  uint32_t u; asm("cvt.rna.tf32.f32 %0, %1;" : "=r"(u) : "f"(f)); return u;
}
__device__ __forceinline__ void mma_tf32(float& c0, float& c1, float& c2, float& c3,
                                         uint32_t a0, uint32_t a1, uint32_t a2, uint32_t a3,
                                         uint32_t b0, uint32_t b1){
  asm volatile("mma.sync.aligned.m16n8k8.row.col.f32.tf32.tf32.f32 "
               "{%0,%1,%2,%3}, {%4,%5,%6,%7}, {%8,%9}, {%0,%1,%2,%3};"
               : "+f"(c0), "+f"(c1), "+f"(c2), "+f"(c3)
               : "r"(a0), "r"(a1), "r"(a2), "r"(a3), "r"(b0), "r"(b1));
}

// ================= scratch =================
__device__ int   g_count[NN];
__device__ int   g_rowptr[NN+1];
__device__ int   g_cursor[NN];
__device__ int   g_part[256];
__device__ int   g_poff[256];
__device__ int   g_esrc[NE];
__device__ float g_ew[NE];
__device__ float g_dis[NN];
__device__ float g_selfn[NN];
__device__ float g_h[(size_t)NN*HIDD];
__device__ float g_agg[(size_t)NN*HIDD];
__device__ float g_qkv[(size_t)NN*3*HIDD];
__device__ float g_attno[(size_t)NN*HIDD];

// ================= CSR build =================
__global__ void zero_count_kernel(){
  int n = blockIdx.x*blockDim.x + threadIdx.x;
  if(n < NN) g_count[n] = 0;
}
__global__ void count_kernel(const int* __restrict__ dst){
  int e = blockIdx.x*blockDim.x + threadIdx.x;
  if(e < NE) atomicAdd(&g_count[dst[e]], 1);
}
__global__ void deg_kernel(){
  int n = blockIdx.x*blockDim.x + threadIdx.x;
  if(n >= NN) return;
  float dis = rsqrtf((float)(g_count[n] + 1));
  g_dis[n] = dis;
  g_selfn[n] = dis*dis;
}
__global__ void scan1_kernel(){
  __shared__ int wsum[8];
  int b = blockIdx.x, t = threadIdx.x;
  int i = b*256 + t;
  int c = g_count[i];
  int lane = t & 31, w = t >> 5;
  int v = c;
  #pragma unroll
  for(int o=1;o<32;o<<=1){ int u=__shfl_up_sync(0xffffffffu,v,o); if(lane>=o) v+=u; }
  if(lane==31) wsum[w]=v;
  __syncthreads();
  if(w==0){
    int s = (lane<8)? wsum[lane] : 0;
    #pragma unroll
    for(int o=1;o<8;o<<=1){ int u=__shfl_up_sync(0xffffffffu,s,o); if(lane>=o) s+=u; }
    if(lane<8) wsum[lane]=s;
  }
  __syncthreads();
  int excl = v - c + (w ? wsum[w-1] : 0);
  g_rowptr[i] = excl;
  if(t==255) g_part[b] = excl + c;
}
__global__ void scan2_kernel(){
  __shared__ int wsum[8];
  int t = threadIdx.x;
  int v = g_part[t];
  int lane = t & 31, w = t >> 5;
  int s = v;
  #pragma unroll
  for(int o=1;o<32;o<<=1){ int u=__shfl_up_sync(0xffffffffu,s,o); if(lane>=o) s+=u; }
  if(lane==31) wsum[w]=s;
  __syncthreads();
  if(w==0){
    int x = (lane<8)? wsum[lane] : 0;
    #pragma unroll
    for(int o=1;o<8;o<<=1){ int u=__shfl_up_sync(0xffffffffu,x,o); if(lane>=o) x+=u; }
    if(lane<8) wsum[lane]=x;
  }
  __syncthreads();
  g_poff[t] = s - v + (w ? wsum[w-1] : 0);
}
__global__ void scan3_kernel(){
  int b = blockIdx.x, t = threadIdx.x;
  int i = b*256 + t;
  int r = g_rowptr[i] + g_poff[b];
  g_rowptr[i] = r;
  g_cursor[i] = r;
  if(i == 0) g_rowptr[NN] = NE;
}
__global__ void fill_kernel(const int* __restrict__ src, const int* __restrict__ dst){
  int e = blockIdx.x*blockDim.x + threadIdx.x;
  if(e >= NE) return;
  int s = src[e], d = dst[e];
  int pos = atomicAdd(&g_cursor[d], 1);
  g_esrc[pos] = s;
  g_ew[pos] = g_dis[s]*g_dis[d];
}

// ================= aggregation (warp per node, gather-only) =================
__global__ void agg64_kernel(const float* __restrict__ hin, float* __restrict__ out){
  int gw = (blockIdx.x*blockDim.x + threadIdx.x) >> 5;
  int lane = threadIdx.x & 31;
  if(gw >= NN) return;
  float2 a = *((const float2*)(hin + (size_t)gw*INDIM) + lane);
  float sn = g_selfn[gw];
  a.x *= sn; a.y *= sn;
  int beg = g_rowptr[gw], end = g_rowptr[gw+1];
  for(int e = beg; e < end; e++){
    int s = g_esrc[e];
    float w = g_ew[e];
    float2 v = *((const float2*)(hin + (size_t)s*INDIM) + lane);
    a.x += w*v.x; a.y += w*v.y;
  }
  *((float2*)(out + (size_t)gw*INDIM) + lane) = a;
}
__global__ void agg128_kernel(const float* __restrict__ hin, float* __restrict__ out){
  int gw = (blockIdx.x*blockDim.x + threadIdx.x) >> 5;
  int lane = threadIdx.x & 31;
  if(gw >= NN) return;
  float4 a = *((const float4*)(hin + (size_t)gw*HIDD) + lane);
  float sn = g_selfn[gw];
  a.x *= sn; a.y *= sn; a.z *= sn; a.w *= sn;
  int beg = g_rowptr[gw], end = g_rowptr[gw+1];
  for(int e = beg; e < end; e++){
    int s = g_esrc[e];
    float w = g_ew[e];
    float4 v = *((const float4*)(hin + (size_t)s*HIDD) + lane);
    a.x += w*v.x; a.y += w*v.y; a.z += w*v.z; a.w += w*v.w;
  }
  *((float4*)(out + (size_t)gw*HIDD) + lane) = a;
}

// ================= tf32 mma.sync GEMM =================
// C[128 x 128 tile] = A[M,KK] x Bop (+bias, optional BN+ReLU), fp32 accumulate.
// BT=1: B is [Ncols, KK] row-major (x @ W^T).  BT=0: B is [KK, Ndt] (h @ W).
// smem: As[128][KK+4], Bs[128][KK+4] (Bs[n][k] = Bmma[k][n]); stride%32==4 -> conflict-free.
// NOTE: ks loop is unroll-1 to keep live regs ~90 and avoid the R5 spill.
template<int BT, int EPI, int KK>
__global__ __launch_bounds__(256)
void gemm_mma_kernel(const float* __restrict__ A, const float* __restrict__ B,
                     const float* __restrict__ bias,
                     const float* __restrict__ bng, const float* __restrict__ bnb,
                     const float* __restrict__ bnm, const float* __restrict__ bnv,
                     float* __restrict__ C, int Ndt)
{
  constexpr int SA = KK + 4;
  extern __shared__ uint32_t sm[];
  uint32_t* As = sm;              // [128][SA]
  uint32_t* Bs = sm + 128*SA;     // [128][SA]
  const int tid = threadIdx.x;
  const int lane = tid & 31, wid = tid >> 5;
  const int row0 = blockIdx.x * 128;
  const int col0 = blockIdx.y * 128;

  constexpr int KQ = KK/4;
  for(int idx = tid; idx < 128*KQ; idx += 256){
    int r = idx / KQ, q = idx % KQ;
    float4 v = *(const float4*)(A + (size_t)(row0 + r)*KK + q*4);
    uint32_t* d = As + r*SA + q*4;
    d[0]=f2tf32(v.x); d[1]=f2tf32(v.y); d[2]=f2tf32(v.z); d[3]=f2tf32(v.w);
  }
  if(BT){
    for(int idx = tid; idx < 128*KQ; idx += 256){
      int r = idx / KQ, q = idx % KQ;
      float4 v = *(const float4*)(B + (size_t)(col0 + r)*KK + q*4);
      uint32_t* d = Bs + r*SA + q*4;
      d[0]=f2tf32(v.x); d[1]=f2tf32(v.y); d[2]=f2tf32(v.z); d[3]=f2tf32(v.w);
    }
  } else {
    for(int idx = tid; idx < KK*32; idx += 256){
      int k = idx >> 5, n4 = idx & 31;
      float4 v = *(const float4*)(B + (size_t)k*Ndt + col0 + n4*4);
      Bs[(n4*4+0)*SA + k] = f2tf32(v.x);
      Bs[(n4*4+1)*SA + k] = f2tf32(v.y);
      Bs[(n4*4+2)*SA + k] = f2tf32(v.z);
      Bs[(n4*4+3)*SA + k] = f2tf32(v.w);
    }
  }
  __syncthreads();

  const int m0 = (wid >> 1) * 32;     // warp tile: 32 rows x 64 cols
  const int n0 = (wid & 1) * 64;
  const int g  = lane >> 2;
  const int t4 = lane & 3;

  float acc[2][8][4];
  #pragma unroll
  for(int i=0;i<2;i++)
    #pragma unroll
    for(int j=0;j<8;j++)
      #pragma unroll
      for(int q=0;q<4;q++) acc[i][j][q]=0.f;

  const uint32_t* Aw0 = As + (m0 + g)*SA + t4;
  const uint32_t* Aw1 = As + (m0 + 16 + g)*SA + t4;
  const uint32_t* Bw  = Bs + (n0 + g)*SA + t4;

  #pragma unroll 1
  for(int ks = 0; ks < KK/8; ks++){
    const int k0 = ks*8;
    uint32_t af[2][4];
    af[0][0] = Aw0[k0];       af[0][1] = Aw0[8*SA + k0];
    af[0][2] = Aw0[k0 + 4];   af[0][3] = Aw0[8*SA + k0 + 4];
    af[1][0] = Aw1[k0];       af[1][1] = Aw1[8*SA + k0];
    af[1][2] = Aw1[k0 + 4];   af[1][3] = Aw1[8*SA + k0 + 4];
    #pragma unroll
    for(int nj = 0; nj < 8; nj++){
      uint32_t b0 = Bw[nj*8*SA + k0];
      uint32_t b1 = Bw[nj*8*SA + k0 + 4];
      mma_tf32(acc[0][nj][0], acc[0][nj][1], acc[0][nj][2], acc[0][nj][3],
               af[0][0], af[0][1], af[0][2], af[0][3], b0, b1);
      mma_tf32(acc[1][nj][0], acc[1][nj][1], acc[1][nj][2], acc[1][nj][3],
               af[1][0], af[1][1], af[1][2], af[1][3], b0, b1);
    }
  }

  #pragma unroll
  for(int mi = 0; mi < 2; mi++){
    #pragma unroll
    for(int nj = 0; nj < 8; nj++){
      int c = col0 + n0 + nj*8 + t4*2;
      float s0, s1;
      if(EPI){
        s0 = bng[c  ]*rsqrtf(bnv[c  ] + BN_EPS);
        s1 = bng[c+1]*rsqrtf(bnv[c+1] + BN_EPS);
      }
      #pragma unroll
      for(int h = 0; h < 2; h++){
        int r = row0 + m0 + mi*16 + g + h*8;
        float v0 = acc[mi][nj][h*2+0] + bias[c];
        float v1 = acc[mi][nj][h*2+1] + bias[c+1];
        if(EPI){
          v0 = fmaxf((v0 - bnm[c  ])*s0 + bnb[c  ], 0.f);
          v1 = fmaxf((v1 - bnm[c+1])*s1 + bnb[c+1], 0.f);
        }
        *(float2*)(C + (size_t)r*Ndt + c) = make_float2(v0, v1);
      }
    }
  }
}

// ================= attention: CTA per (graph, head, half) =================
// Each CTA handles 8 of the 16 q-tiles -> grid 1024 (better wave quantization).
// smem: Ks[512][36] | Vs[512][32] | Qs[32][32] | S[32][516]
__global__ __launch_bounds__(256)
void attn_kernel(const float* __restrict__ qkv, float* __restrict__ out){
  extern __shared__ float smf[];
  float* Ks = smf;                  // 512*36
  float* Vs = Ks + 512*36;          // 512*32
  float* Qs = Vs + 512*32;          // 32*32
  float* S  = Qs + 32*32;           // 32*516
  int g    = blockIdx.x >> 3;
  int hd   = (blockIdx.x >> 1) & 3;
  int half = blockIdx.x & 1;
  int n0 = g*PN;
  int t = threadIdx.x;
  int lane = t & 31, warp = t >> 5;
  const float scale = 0.17677669529663687f;  // 1/sqrt(32)

  for(int idx = t; idx < PN*8; idx += 256){
    int r = idx >> 3, d4 = idx & 7;
    const float* row = qkv + (size_t)(n0 + r)*384 + hd*32;
    *(float4*)(Ks + r*36 + d4*4) = *(const float4*)(row + 128 + d4*4);
    *(float4*)(Vs + r*32 + d4*4) = *(const float4*)(row + 256 + d4*4);
  }
  __syncthreads();

  for(int qi8 = 0; qi8 < 8; qi8++){
    int qt = half*8 + qi8;
    for(int idx = t; idx < 32*8; idx += 256){
      int r = idx >> 3, d4 = idx & 7;
      *(float4*)(Qs + r*32 + d4*4) =
        *(const float4*)(qkv + (size_t)(n0 + qt*32 + r)*384 + hd*32 + d4*4);
    }
    __syncthreads();

    // Phase A: S = Q K^T * scale
    int r0 = warp*4;
    for(int kb = 0; kb < 4; kb++){
      float acc[4][4] = {};
      const float* kb0 = Ks + (kb*128 + lane)*36;
      #pragma unroll
      for(int d4 = 0; d4 < 8; d4++){
        float4 q[4], kk[4];
        #pragma unroll
        for(int i=0;i<4;i++) q[i]  = *(const float4*)(Qs + (r0+i)*32 + d4*4);
        #pragma unroll
        for(int j=0;j<4;j++) kk[j] = *(const float4*)(kb0 + j*32*36 + d4*4);
        #pragma unroll
        for(int i=0;i<4;i++)
          #pragma unroll
          for(int j=0;j<4;j++)
            acc[i][j] += q[i].x*kk[j].x + q[i].y*kk[j].y + q[i].z*kk[j].z + q[i].w*kk[j].w;
      }
      #pragma unroll
      for(int i=0;i<4;i++)
        #pragma unroll
        for(int j=0;j<4;j++)
          S[(r0+i)*516 + kb*128 + j*32 + lane] = acc[i][j]*scale;
    }
    __syncthreads();

    // Phase B: row softmax
    for(int rr = 0; rr < 4; rr++){
      int r = warp*4 + rr;
      float mx = -1e30f;
      for(int j = lane; j < 512; j += 32) mx = fmaxf(mx, S[r*516 + j]);
      #pragma unroll
      for(int o=16;o;o>>=1) mx = fmaxf(mx, __shfl_xor_sync(0xffffffffu, mx, o));
      float sum = 0.f;
      for(int j = lane; j < 512; j += 32){
        float e = __expf(S[r*516 + j] - mx);
        S[r*516 + j] = e;
        sum += e;
      }
      #pragma unroll
      for(int o=16;o;o>>=1) sum += __shfl_xor_sync(0xffffffffu, sum, o);
      float inv = 1.f/sum;
      for(int j = lane; j < 512; j += 32) S[r*516 + j] *= inv;
    }
    __syncthreads();

    // Phase C: O = P V
    {
      int qi = t >> 3;
      int dbase = (t & 7)*4;
      float o0=0,o1=0,o2=0,o3=0;
      const float* Srow = S + qi*516;
      #pragma unroll 4
      for(int j4 = 0; j4 < 128; j4++){
        float4 p  = *(const float4*)(Srow + j4*4);
        float4 v0 = *(const float4*)(Vs + (j4*4+0)*32 + dbase);
        float4 v1 = *(const float4*)(Vs + (j4*4+1)*32 + dbase);
        float4 v2 = *(const float4*)(Vs + (j4*4+2)*32 + dbase);
        float4 v3 = *(const float4*)(Vs + (j4*4+3)*32 + dbase);
        o0 += p.x*v0.x + p.y*v1.x + p.z*v2.x + p.w*v3.x;
        o1 += p.x*v0.y + p.y*v1.y + p.z*v2.y + p.w*v3.y;
        o2 += p.x*v0.z + p.y*v1.z + p.z*v2.z + p.w*v3.z;
        o3 += p.x*v0.w + p.y*v1.w + p.z*v2.w + p.w*v3.w;
      }
      int n = n0 + qt*32 + qi;
      *(float4*)(out + (size_t)n*HIDD + hd*32 + dbase) = make_float4(o0,o1,o2,o3);
    }
    __syncthreads();
  }
}

// ================= mean pool =================
__global__ void pool_kernel(const float* __restrict__ fin, float* __restrict__ emb){
  int g = blockIdx.x, d = threadIdx.x;
  float s = 0.f;
  const float* base = fin + (size_t)g*PN*HIDD + d;
  for(int i = 0; i < PN; i++) s += base[(size_t)i*HIDD];
  emb[g*HIDD + d] = s * (1.0f/PN);
}

// ================= launch =================
extern "C" void kernel_launch(void* const* d_in, const int* in_sizes, int n_in,
                              void* d_out, int out_size) {
  const float* x   = (const float*)d_in[0];
  const float* W0  = (const float*)d_in[1];
  const float* b0  = (const float*)d_in[2];
  const float* Wh  = (const float*)d_in[3];
  const float* bh  = (const float*)d_in[4];
  const float* bng = (const float*)d_in[5];
  const float* bnb = (const float*)d_in[6];
  const float* bnm = (const float*)d_in[7];
  const float* bnv = (const float*)d_in[8];
  const float* aiw = (const float*)d_in[9];
  const float* aib = (const float*)d_in[10];
  const float* aow = (const float*)d_in[11];
  const float* aob = (const float*)d_in[12];
  const int*  eidx = (const int*)d_in[13];

  float* out_final = (float*)d_out;
  float* out_emb   = out_final + (size_t)NN*HIDD;

  const int* src = eidx;
  const int* dst = eidx + NE;

  float *p_h, *p_agg, *p_qkv, *p_attno;
  cudaGetSymbolAddress((void**)&p_h,     g_h);
  cudaGetSymbolAddress((void**)&p_agg,   g_agg);
  cudaGetSymbolAddress((void**)&p_qkv,   g_qkv);
  cudaGetSymbolAddress((void**)&p_attno, g_attno);

  const int GEMM_SMEM64  = 2*128*68*4;    // 69632
  const int GEMM_SMEM128 = 2*128*132*4;   // 135168
  const int ATTN_SMEM = (512*36 + 512*32 + 32*32 + 32*516)*4;  // 209408
  cudaFuncSetAttribute(gemm_mma_kernel<0,1,64>,  cudaFuncAttributeMaxDynamicSharedMemorySize, GEMM_SMEM64);
  cudaFuncSetAttribute(gemm_mma_kernel<0,1,128>, cudaFuncAttributeMaxDynamicSharedMemorySize, GEMM_SMEM128);
  cudaFuncSetAttribute(gemm_mma_kernel<1,0,128>, cudaFuncAttributeMaxDynamicSharedMemorySize, GEMM_SMEM128);
  cudaFuncSetAttribute(attn_kernel,              cudaFuncAttributeMaxDynamicSharedMemorySize, ATTN_SMEM);

  // CSR build
  zero_count_kernel<<<NN/256, 256>>>();
  count_kernel<<<NE/256, 256>>>(dst);
  deg_kernel<<<NN/256, 256>>>();
  scan1_kernel<<<256, 256>>>();
  scan2_kernel<<<1, 256>>>();
  scan3_kernel<<<256, 256>>>();
  fill_kernel<<<NE/256, 256>>>(src, dst);

  // layer 0: aggregate in input space (64-d), then tf32 GEMM + BN + ReLU
  agg64_kernel<<<NN*32/256, 256>>>(x, p_agg);
  gemm_mma_kernel<0,1,64><<<dim3(512,1), 256, GEMM_SMEM64>>>(
      p_agg, W0, b0, bng, bnb, bnm, bnv, p_h, 128);

  // layers 1..3
  for(int l = 0; l < 3; l++){
    agg128_kernel<<<NN*32/256, 256>>>(p_h, p_agg);
    gemm_mma_kernel<0,1,128><<<dim3(512,1), 256, GEMM_SMEM128>>>(
        p_agg, Wh + (size_t)l*HIDD*HIDD, bh + l*HIDD,
        bng + (l+1)*HIDD, bnb + (l+1)*HIDD, bnm + (l+1)*HIDD, bnv + (l+1)*HIDD,
        p_h, 128);
  }

  // qkv projection: [N,128] @ attn_in_w^T -> [N,384]
  gemm_mma_kernel<1,0,128><<<dim3(512,3), 256, GEMM_SMEM128>>>(
      p_h, aiw, aib, nullptr, nullptr, nullptr, nullptr, p_qkv, 384);

  // attention per (graph, head, half)
  attn_kernel<<<NG*4*2, 256, ATTN_SMEM>>>(p_qkv, p_attno);

  // output projection -> final
  gemm_mma_kernel<1,0,128><<<dim3(512,1), 256, GEMM_SMEM128>>>(
      p_attno, aow, aob, nullptr, nullptr, nullptr, nullptr, out_final, 128);

  // mean pool -> graph_emb
  pool_kernel<<<NG, HIDD>>>(out_final, out_emb);
}

// round 7
// speedup vs baseline: 2.5296x; 1.5437x over previous
#include <cuda_runtime.h>
#include <cstdint>

#define NN 65536
#define NE (NN*16)
#define NG 128
#define PN 512
#define HIDD 128
#define INDIM 64
#define BN_EPS 1e-5f

__device__ __forceinline__ uint32_t f2tf32(float f){
  uint32_t u; asm("cvt.rna.tf32.f32 %0, %1;" : "=r"(u) : "f"(f)); return u;
}
__device__ __forceinline__ void mma_tf32(float& c0, float& c1, float& c2, float& c3,
                                         uint32_t a0, uint32_t a1, uint32_t a2, uint32_t a3,
                                         uint32_t b0, uint32_t b1){
  asm volatile("mma.sync.aligned.m16n8k8.row.col.f32.tf32.tf32.f32 "
               "{%0,%1,%2,%3}, {%4,%5,%6,%7}, {%8,%9}, {%0,%1,%2,%3};"
               : "+f"(c0), "+f"(c1), "+f"(c2), "+f"(c3)
               : "r"(a0), "r"(a1), "r"(a2), "r"(a3), "r"(b0), "r"(b1));
}

// ================= scratch =================
__device__ int    g_count[NN];
__device__ int    g_rowptr[NN+1];
__device__ int    g_cursor[NN];
__device__ int    g_part[256];
__device__ int    g_poff[256];
__device__ float2 g_edge[NE];     // (src bits, weight)
__device__ float  g_dis[NN];
__device__ float  g_selfn[NN];
__device__ float  g_h[(size_t)NN*HIDD];
__device__ float  g_agg[(size_t)NN*HIDD];
__device__ float  g_qkv[(size_t)NN*3*HIDD];
__device__ float  g_attno[(size_t)NN*HIDD];

// ================= CSR build =================
__global__ void zero_count_kernel(){
  int n = blockIdx.x*blockDim.x + threadIdx.x;
  if(n < NN) g_count[n] = 0;
}
__global__ void count_kernel(const int* __restrict__ dst){
  int e = blockIdx.x*blockDim.x + threadIdx.x;
  if(e < NE) atomicAdd(&g_count[dst[e]], 1);
}
__global__ void deg_kernel(){
  int n = blockIdx.x*blockDim.x + threadIdx.x;
  if(n >= NN) return;
  float dis = rsqrtf((float)(g_count[n] + 1));
  g_dis[n] = dis;
  g_selfn[n] = dis*dis;
}
__global__ void scan1_kernel(){
  __shared__ int wsum[8];
  int b = blockIdx.x, t = threadIdx.x;
  int i = b*256 + t;
  int c = g_count[i];
  int lane = t & 31, w = t >> 5;
  int v = c;
  #pragma unroll
  for(int o=1;o<32;o<<=1){ int u=__shfl_up_sync(0xffffffffu,v,o); if(lane>=o) v+=u; }
  if(lane==31) wsum[w]=v;
  __syncthreads();
  if(w==0){
    int s = (lane<8)? wsum[lane] : 0;
    #pragma unroll
    for(int o=1;o<8;o<<=1){ int u=__shfl_up_sync(0xffffffffu,s,o); if(lane>=o) s+=u; }
    if(lane<8) wsum[lane]=s;
  }
  __syncthreads();
  int excl = v - c + (w ? wsum[w-1] : 0);
  g_rowptr[i] = excl;
  if(t==255) g_part[b] = excl + c;
}
__global__ void scan2_kernel(){
  __shared__ int wsum[8];
  int t = threadIdx.x;
  int v = g_part[t];
  int lane = t & 31, w = t >> 5;
  int s = v;
  #pragma unroll
  for(int o=1;o<32;o<<=1){ int u=__shfl_up_sync(0xffffffffu,s,o); if(lane>=o) s+=u; }
  if(lane==31) wsum[w]=s;
  __syncthreads();
  if(w==0){
    int x = (lane<8)? wsum[lane] : 0;
    #pragma unroll
    for(int o=1;o<8;o<<=1){ int u=__shfl_up_sync(0xffffffffu,x,o); if(lane>=o) x+=u; }
    if(lane<8) wsum[lane]=x;
  }
  __syncthreads();
  g_poff[t] = s - v + (w ? wsum[w-1] : 0);
}
__global__ void scan3_kernel(){
  int b = blockIdx.x, t = threadIdx.x;
  int i = b*256 + t;
  int r = g_rowptr[i] + g_poff[b];
  g_rowptr[i] = r;
  g_cursor[i] = r;
  if(i == 0) g_rowptr[NN] = NE;
}
__global__ void fill_kernel(const int* __restrict__ src, const int* __restrict__ dst){
  int e = blockIdx.x*blockDim.x + threadIdx.x;
  if(e >= NE) return;
  int s = src[e], d = dst[e];
  int pos = atomicAdd(&g_cursor[d], 1);
  g_edge[pos] = make_float2(__int_as_float(s), g_dis[s]*g_dis[d]);
}

// ================= aggregation (warp per node, gather-only) =================
__global__ void agg64_kernel(const float* __restrict__ hin, float* __restrict__ out){
  int gw = (blockIdx.x*blockDim.x + threadIdx.x) >> 5;
  int lane = threadIdx.x & 31;
  if(gw >= NN) return;
  float2 a = *((const float2*)(hin + (size_t)gw*INDIM) + lane);
  float sn = g_selfn[gw];
  a.x *= sn; a.y *= sn;
  int beg = g_rowptr[gw], end = g_rowptr[gw+1];
  for(int e = beg; e < end; e++){
    float2 ed = g_edge[e];
    int s = __float_as_int(ed.x);
    float w = ed.y;
    float2 v = *((const float2*)(hin + (size_t)s*INDIM) + lane);
    a.x += w*v.x; a.y += w*v.y;
  }
  *((float2*)(out + (size_t)gw*INDIM) + lane) = a;
}
__global__ void agg128_kernel(const float* __restrict__ hin, float* __restrict__ out){
  int gw = (blockIdx.x*blockDim.x + threadIdx.x) >> 5;
  int lane = threadIdx.x & 31;
  if(gw >= NN) return;
  float4 a = *((const float4*)(hin + (size_t)gw*HIDD) + lane);
  float sn = g_selfn[gw];
  a.x *= sn; a.y *= sn; a.z *= sn; a.w *= sn;
  int beg = g_rowptr[gw], end = g_rowptr[gw+1];
  for(int e = beg; e < end; e++){
    float2 ed = g_edge[e];
    int s = __float_as_int(ed.x);
    float w = ed.y;
    float4 v = *((const float4*)(hin + (size_t)s*HIDD) + lane);
    a.x += w*v.x; a.y += w*v.y; a.z += w*v.z; a.w += w*v.w;
  }
  *((float4*)(out + (size_t)gw*HIDD) + lane) = a;
}

// ================= tf32 mma.sync GEMM (unchanged from R6) =================
template<int BT, int EPI, int KK>
__global__ __launch_bounds__(256)
void gemm_mma_kernel(const float* __restrict__ A, const float* __restrict__ B,
                     const float* __restrict__ bias,
                     const float* __restrict__ bng, const float* __restrict__ bnb,
                     const float* __restrict__ bnm, const float* __restrict__ bnv,
                     float* __restrict__ C, int Ndt)
{
  constexpr int SA = KK + 4;
  extern __shared__ uint32_t sm[];
  uint32_t* As = sm;
  uint32_t* Bs = sm + 128*SA;
  const int tid = threadIdx.x;
  const int lane = tid & 31, wid = tid >> 5;
  const int row0 = blockIdx.x * 128;
  const int col0 = blockIdx.y * 128;

  constexpr int KQ = KK/4;
  for(int idx = tid; idx < 128*KQ; idx += 256){
    int r = idx / KQ, q = idx % KQ;
    float4 v = *(const float4*)(A + (size_t)(row0 + r)*KK + q*4);
    uint32_t* d = As + r*SA + q*4;
    d[0]=f2tf32(v.x); d[1]=f2tf32(v.y); d[2]=f2tf32(v.z); d[3]=f2tf32(v.w);
  }
  if(BT){
    for(int idx = tid; idx < 128*KQ; idx += 256){
      int r = idx / KQ, q = idx % KQ;
      float4 v = *(const float4*)(B + (size_t)(col0 + r)*KK + q*4);
      uint32_t* d = Bs + r*SA + q*4;
      d[0]=f2tf32(v.x); d[1]=f2tf32(v.y); d[2]=f2tf32(v.z); d[3]=f2tf32(v.w);
    }
  } else {
    for(int idx = tid; idx < KK*32; idx += 256){
      int k = idx >> 5, n4 = idx & 31;
      float4 v = *(const float4*)(B + (size_t)k*Ndt + col0 + n4*4);
      Bs[(n4*4+0)*SA + k] = f2tf32(v.x);
      Bs[(n4*4+1)*SA + k] = f2tf32(v.y);
      Bs[(n4*4+2)*SA + k] = f2tf32(v.z);
      Bs[(n4*4+3)*SA + k] = f2tf32(v.w);
    }
  }
  __syncthreads();

  const int m0 = (wid >> 1) * 32;
  const int n0 = (wid & 1) * 64;
  const int g  = lane >> 2;
  const int t4 = lane & 3;

  float acc[2][8][4];
  #pragma unroll
  for(int i=0;i<2;i++)
    #pragma unroll
    for(int j=0;j<8;j++)
      #pragma unroll
      for(int q=0;q<4;q++) acc[i][j][q]=0.f;

  const uint32_t* Aw0 = As + (m0 + g)*SA + t4;
  const uint32_t* Aw1 = As + (m0 + 16 + g)*SA + t4;
  const uint32_t* Bw  = Bs + (n0 + g)*SA + t4;

  #pragma unroll 1
  for(int ks = 0; ks < KK/8; ks++){
    const int k0 = ks*8;
    uint32_t af[2][4];
    af[0][0] = Aw0[k0];       af[0][1] = Aw0[8*SA + k0];
    af[0][2] = Aw0[k0 + 4];   af[0][3] = Aw0[8*SA + k0 + 4];
    af[1][0] = Aw1[k0];       af[1][1] = Aw1[8*SA + k0];
    af[1][2] = Aw1[k0 + 4];   af[1][3] = Aw1[8*SA + k0 + 4];
    #pragma unroll
    for(int nj = 0; nj < 8; nj++){
      uint32_t b0 = Bw[nj*8*SA + k0];
      uint32_t b1 = Bw[nj*8*SA + k0 + 4];
      mma_tf32(acc[0][nj][0], acc[0][nj][1], acc[0][nj][2], acc[0][nj][3],
               af[0][0], af[0][1], af[0][2], af[0][3], b0, b1);
      mma_tf32(acc[1][nj][0], acc[1][nj][1], acc[1][nj][2], acc[1][nj][3],
               af[1][0], af[1][1], af[1][2], af[1][3], b0, b1);
    }
  }

  #pragma unroll
  for(int mi = 0; mi < 2; mi++){
    #pragma unroll
    for(int nj = 0; nj < 8; nj++){
      int c = col0 + n0 + nj*8 + t4*2;
      float s0, s1;
      if(EPI){
        s0 = bng[c  ]*rsqrtf(bnv[c  ] + BN_EPS);
        s1 = bng[c+1]*rsqrtf(bnv[c+1] + BN_EPS);
      }
      #pragma unroll
      for(int h = 0; h < 2; h++){
        int r = row0 + m0 + mi*16 + g + h*8;
        float v0 = acc[mi][nj][h*2+0] + bias[c];
        float v1 = acc[mi][nj][h*2+1] + bias[c+1];
        if(EPI){
          v0 = fmaxf((v0 - bnm[c  ])*s0 + bnb[c  ], 0.f);
          v1 = fmaxf((v1 - bnm[c+1])*s1 + bnb[c+1], 0.f);
        }
        *(float2*)(C + (size_t)r*Ndt + c) = make_float2(v0, v1);
      }
    }
  }
}

// ================= attention via tf32 mma: CTA per (graph, head, half) ===========
// smem floats: Ks[512][36] | Vs[512][40] | S[32][516] | QP = max(Qs[32][36], part[2][32][36])
#define KSTR 36
#define VSTR 40
#define SSTR 516
#define PSTR 36
#define KS_OFF 0
#define VS_OFF (512*KSTR)                 // 18432
#define S_OFF  (VS_OFF + 512*VSTR)        // 38912
#define QP_OFF (S_OFF + 32*SSTR)          // 55424
#define ATTN_FLOATS (QP_OFF + 2*32*PSTR)  // 57728

__global__ __launch_bounds__(256)
void attn_mma_kernel(const float* __restrict__ qkv, float* __restrict__ out){
  extern __shared__ float smf[];
  float* Ks = smf + KS_OFF;
  float* Vs = smf + VS_OFF;
  float* S  = smf + S_OFF;
  float* QP = smf + QP_OFF;
  uint32_t* Ku = (uint32_t*)Ks;
  uint32_t* Vu = (uint32_t*)Vs;
  uint32_t* Su = (uint32_t*)S;
  uint32_t* Qu = (uint32_t*)QP;

  int g    = blockIdx.x >> 3;
  int hd   = (blockIdx.x >> 1) & 3;
  int half = blockIdx.x & 1;
  int n0 = g*PN;
  int t = threadIdx.x;
  int lane = t & 31, warp = t >> 5;
  int gq = lane >> 2, t4 = lane & 3;
  const float scale = 0.17677669529663687f;  // 1/sqrt(32)

  // stage K,V tf32-rounded
  for(int idx = t; idx < PN*8; idx += 256){
    int r = idx >> 3, d4 = (idx & 7)*4;
    const float* row = qkv + (size_t)(n0 + r)*384 + hd*32;
    float4 kv = *(const float4*)(row + 128 + d4);
    float4 vv = *(const float4*)(row + 256 + d4);
    uint32_t* kd = Ku + r*KSTR + d4;
    kd[0]=f2tf32(kv.x); kd[1]=f2tf32(kv.y); kd[2]=f2tf32(kv.z); kd[3]=f2tf32(kv.w);
    uint32_t* vd = Vu + r*VSTR + d4;
    vd[0]=f2tf32(vv.x); vd[1]=f2tf32(vv.y); vd[2]=f2tf32(vv.z); vd[3]=f2tf32(vv.w);
  }
  __syncthreads();

  for(int qi8 = 0; qi8 < 8; qi8++){
    int qt = half*8 + qi8;
    // stage Q tile tf32-rounded
    for(int idx = t; idx < 32*8; idx += 256){
      int r = idx >> 3, d4 = (idx & 7)*4;
      float4 qv = *(const float4*)(qkv + (size_t)(n0 + qt*32 + r)*384 + hd*32 + d4);
      uint32_t* qd = Qu + r*PSTR + d4;
      qd[0]=f2tf32(qv.x); qd[1]=f2tf32(qv.y); qd[2]=f2tf32(qv.z); qd[3]=f2tf32(qv.w);
    }
    __syncthreads();

    // Phase A: S[0..32][warp*64 .. +64] = Q K^T * scale
    {
      float c[2][8][4];
      #pragma unroll
      for(int i=0;i<2;i++)
        #pragma unroll
        for(int j=0;j<8;j++)
          #pragma unroll
          for(int q=0;q<4;q++) c[i][j][q]=0.f;

      #pragma unroll 1
      for(int ks = 0; ks < 4; ks++){
        int k0 = ks*8;
        uint32_t a[2][4];
        #pragma unroll
        for(int mi=0;mi<2;mi++){
          const uint32_t* qb = Qu + (mi*16+gq)*PSTR + k0 + t4;
          a[mi][0]=qb[0]; a[mi][1]=qb[8*PSTR]; a[mi][2]=qb[4]; a[mi][3]=qb[8*PSTR+4];
        }
        #pragma unroll
        for(int nj=0;nj<8;nj++){
          const uint32_t* kb = Ku + (warp*64+nj*8+gq)*KSTR + k0 + t4;
          uint32_t b0 = kb[0], b1 = kb[4];
          mma_tf32(c[0][nj][0],c[0][nj][1],c[0][nj][2],c[0][nj][3],
                   a[0][0],a[0][1],a[0][2],a[0][3], b0,b1);
          mma_tf32(c[1][nj][0],c[1][nj][1],c[1][nj][2],c[1][nj][3],
                   a[1][0],a[1][1],a[1][2],a[1][3], b0,b1);
        }
      }
      #pragma unroll
      for(int mi=0;mi<2;mi++)
        #pragma unroll
        for(int nj=0;nj<8;nj++){
          float* sp = S + (mi*16+gq)*SSTR + warp*64 + nj*8 + t4*2;
          sp[0] = c[mi][nj][0]*scale;
          sp[1] = c[mi][nj][1]*scale;
          sp[8*SSTR+0] = c[mi][nj][2]*scale;
          sp[8*SSTR+1] = c[mi][nj][3]*scale;
        }
    }
    __syncthreads();

    // Phase B: row softmax; store P tf32-rounded
    for(int rr = 0; rr < 4; rr++){
      int r = warp*4 + rr;
      float mx = -1e30f;
      for(int j = lane; j < 512; j += 32) mx = fmaxf(mx, S[r*SSTR + j]);
      #pragma unroll
      for(int o=16;o;o>>=1) mx = fmaxf(mx, __shfl_xor_sync(0xffffffffu, mx, o));
      float sum = 0.f;
      for(int j = lane; j < 512; j += 32){
        float e = __expf(S[r*SSTR + j] - mx);
        S[r*SSTR + j] = e;
        sum += e;
      }
      #pragma unroll
      for(int o=16;o;o>>=1) sum += __shfl_xor_sync(0xffffffffu, sum, o);
      float inv = 1.f/sum;
      for(int j = lane; j < 512; j += 32)
        S[r*SSTR + j] = __uint_as_float(f2tf32(S[r*SSTR + j]*inv));
    }
    __syncthreads();

    // Phase C: O = P V  (warps: 2q x 2n x 2k; partial over k-chunks)
    {
      int wq = warp & 1, wn = (warp >> 1) & 1, wk = warp >> 2;
      float c[2][4] = {};
      #pragma unroll 2
      for(int ks = 0; ks < 32; ks++){
        int k0 = wk*256 + ks*8;
        const uint32_t* pb = Su + (wq*16+gq)*SSTR + k0 + t4;
        uint32_t a0 = pb[0], a1 = pb[8*SSTR], a2 = pb[4], a3 = pb[8*SSTR+4];
        #pragma unroll
        for(int nj=0;nj<2;nj++){
          const uint32_t* vb = Vu + (k0+t4)*VSTR + wn*16 + nj*8 + gq;
          uint32_t b0 = vb[0], b1 = vb[4*VSTR];
          mma_tf32(c[nj][0],c[nj][1],c[nj][2],c[nj][3], a0,a1,a2,a3, b0,b1);
        }
      }
      float* part = QP + wk*32*PSTR;
      #pragma unroll
      for(int nj=0;nj<2;nj++){
        float* pp = part + (wq*16+gq)*PSTR + wn*16 + nj*8 + t4*2;
        pp[0] = c[nj][0];
        pp[1] = c[nj][1];
        pp[8*PSTR+0] = c[nj][2];
        pp[8*PSTR+1] = c[nj][3];
      }
    }
    __syncthreads();

    // reduce 2 k-partials and write out
    {
      int q = t >> 3, dq = (t & 7)*4;
      float4 p0 = *(float4*)(QP + q*PSTR + dq);
      float4 p1 = *(float4*)(QP + 32*PSTR + q*PSTR + dq);
      float4 o = make_float4(p0.x+p1.x, p0.y+p1.y, p0.z+p1.z, p0.w+p1.w);
      *(float4*)(out + (size_t)(n0 + qt*32 + q)*HIDD + hd*32 + dq) = o;
    }
    __syncthreads();
  }
}

// ================= mean pool =================
__global__ void pool_kernel(const float* __restrict__ fin, float* __restrict__ emb){
  int g = blockIdx.x, d = threadIdx.x;
  float s = 0.f;
  const float* base = fin + (size_t)g*PN*HIDD + d;
  for(int i = 0; i < PN; i++) s += base[(size_t)i*HIDD];
  emb[g*HIDD + d] = s * (1.0f/PN);
}

// ================= launch =================
extern "C" void kernel_launch(void* const* d_in, const int* in_sizes, int n_in,
                              void* d_out, int out_size) {
  const float* x   = (const float*)d_in[0];
  const float* W0  = (const float*)d_in[1];
  const float* b0  = (const float*)d_in[2];
  const float* Wh  = (const float*)d_in[3];
  const float* bh  = (const float*)d_in[4];
  const float* bng = (const float*)d_in[5];
  const float* bnb = (const float*)d_in[6];
  const float* bnm = (const float*)d_in[7];
  const float* bnv = (const float*)d_in[8];
  const float* aiw = (const float*)d_in[9];
  const float* aib = (const float*)d_in[10];
  const float* aow = (const float*)d_in[11];
  const float* aob = (const float*)d_in[12];
  const int*  eidx = (const int*)d_in[13];

  float* out_final = (float*)d_out;
  float* out_emb   = out_final + (size_t)NN*HIDD;

  const int* src = eidx;
  const int* dst = eidx + NE;

  float *p_h, *p_agg, *p_qkv, *p_attno;
  cudaGetSymbolAddress((void**)&p_h,     g_h);
  cudaGetSymbolAddress((void**)&p_agg,   g_agg);
  cudaGetSymbolAddress((void**)&p_qkv,   g_qkv);
  cudaGetSymbolAddress((void**)&p_attno, g_attno);

  const int GEMM_SMEM64  = 2*128*68*4;    // 69632
  const int GEMM_SMEM128 = 2*128*132*4;   // 135168
  const int ATTN_SMEM = ATTN_FLOATS*4;    // 230912
  cudaFuncSetAttribute(gemm_mma_kernel<0,1,64>,  cudaFuncAttributeMaxDynamicSharedMemorySize, GEMM_SMEM64);
  cudaFuncSetAttribute(gemm_mma_kernel<0,1,128>, cudaFuncAttributeMaxDynamicSharedMemorySize, GEMM_SMEM128);
  cudaFuncSetAttribute(gemm_mma_kernel<1,0,128>, cudaFuncAttributeMaxDynamicSharedMemorySize, GEMM_SMEM128);
  cudaFuncSetAttribute(attn_mma_kernel,          cudaFuncAttributeMaxDynamicSharedMemorySize, ATTN_SMEM);

  // CSR build
  zero_count_kernel<<<NN/256, 256>>>();
  count_kernel<<<NE/256, 256>>>(dst);
  deg_kernel<<<NN/256, 256>>>();
  scan1_kernel<<<256, 256>>>();
  scan2_kernel<<<1, 256>>>();
  scan3_kernel<<<256, 256>>>();
  fill_kernel<<<NE/256, 256>>>(src, dst);

  // layer 0: aggregate in input space (64-d), then tf32 GEMM + BN + ReLU
  agg64_kernel<<<NN*32/256, 256>>>(x, p_agg);
  gemm_mma_kernel<0,1,64><<<dim3(512,1), 256, GEMM_SMEM64>>>(
      p_agg, W0, b0, bng, bnb, bnm, bnv, p_h, 128);

  // layers 1..3
  for(int l = 0; l < 3; l++){
    agg128_kernel<<<NN*32/256, 256>>>(p_h, p_agg);
    gemm_mma_kernel<0,1,128><<<dim3(512,1), 256, GEMM_SMEM128>>>(
        p_agg, Wh + (size_t)l*HIDD*HIDD, bh + l*HIDD,
        bng + (l+1)*HIDD, bnb + (l+1)*HIDD, bnm + (l+1)*HIDD, bnv + (l+1)*HIDD,
        p_h, 128);
  }

  // qkv projection: [N,128] @ attn_in_w^T -> [N,384]
  gemm_mma_kernel<1,0,128><<<dim3(512,3), 256, GEMM_SMEM128>>>(
      p_h, aiw, aib, nullptr, nullptr, nullptr, nullptr, p_qkv, 384);

  // attention per (graph, head, half) — tensor cores
  attn_mma_kernel<<<NG*4*2, 256, ATTN_SMEM>>>(p_qkv, p_attno);

  // output projection -> final
  gemm_mma_kernel<1,0,128><<<dim3(512,1), 256, GEMM_SMEM128>>>(
      p_attno, aow, aob, nullptr, nullptr, nullptr, nullptr, out_final, 128);

  // mean pool -> graph_emb
  pool_kernel<<<NG, HIDD>>>(out_final, out_emb);
}

// round 8
// speedup vs baseline: 2.7688x; 1.0945x over previous
#include <cuda_runtime.h>
#include <cstdint>

#define NN 65536
#define NE (NN*16)
#define NG 128
#define PN 512
#define HIDD 128
#define INDIM 64
#define BN_EPS 1e-5f

__device__ __forceinline__ uint32_t f2tf32(float f){
  uint32_t u; asm("cvt.rna.tf32.f32 %0, %1;" : "=r"(u) : "f"(f)); return u;
}
__device__ __forceinline__ void mma_tf32(float& c0, float& c1, float& c2, float& c3,
                                         uint32_t a0, uint32_t a1, uint32_t a2, uint32_t a3,
                                         uint32_t b0, uint32_t b1){
  asm volatile("mma.sync.aligned.m16n8k8.row.col.f32.tf32.tf32.f32 "
               "{%0,%1,%2,%3}, {%4,%5,%6,%7}, {%8,%9}, {%0,%1,%2,%3};"
               : "+f"(c0), "+f"(c1), "+f"(c2), "+f"(c3)
               : "r"(a0), "r"(a1), "r"(a2), "r"(a3), "r"(b0), "r"(b1));
}
__device__ __forceinline__ uint4 q4(float4 v){
  return make_uint4(f2tf32(v.x), f2tf32(v.y), f2tf32(v.z), f2tf32(v.w));
}

// ================= scratch =================
__device__ int    g_count[NN];
__device__ int    g_rowptr[NN+1];
__device__ int    g_cursor[NN];
__device__ int    g_part[256];
__device__ int    g_poff[256];
__device__ float2 g_edge[NE];     // (src bits, weight)
__device__ float  g_dis[NN];
__device__ float  g_selfn[NN];
__device__ float  g_h[(size_t)NN*HIDD];
__device__ float  g_agg[(size_t)NN*HIDD];
__device__ float  g_qkv[(size_t)NN*3*HIDD];
__device__ float  g_attno[(size_t)NN*HIDD];

// ================= CSR build =================
__global__ void count_kernel(const int* __restrict__ dst){
  int e = blockIdx.x*blockDim.x + threadIdx.x;
  if(e < NE) atomicAdd(&g_count[dst[e]], 1);
}
// scan1 also computes per-node degree norms (deg fused)
__global__ void scan1_kernel(){
  __shared__ int wsum[8];
  int b = blockIdx.x, t = threadIdx.x;
  int i = b*256 + t;
  int c = g_count[i];
  float dis = rsqrtf((float)(c + 1));
  g_dis[i] = dis;
  g_selfn[i] = dis*dis;
  int lane = t & 31, w = t >> 5;
  int v = c;
  #pragma unroll
  for(int o=1;o<32;o<<=1){ int u=__shfl_up_sync(0xffffffffu,v,o); if(lane>=o) v+=u; }
  if(lane==31) wsum[w]=v;
  __syncthreads();
  if(w==0){
    int s = (lane<8)? wsum[lane] : 0;
    #pragma unroll
    for(int o=1;o<8;o<<=1){ int u=__shfl_up_sync(0xffffffffu,s,o); if(lane>=o) s+=u; }
    if(lane<8) wsum[lane]=s;
  }
  __syncthreads();
  int excl = v - c + (w ? wsum[w-1] : 0);
  g_rowptr[i] = excl;
  if(t==255) g_part[b] = excl + c;
}
__global__ void scan2_kernel(){
  __shared__ int wsum[8];
  int t = threadIdx.x;
  int v = g_part[t];
  int lane = t & 31, w = t >> 5;
  int s = v;
  #pragma unroll
  for(int o=1;o<32;o<<=1){ int u=__shfl_up_sync(0xffffffffu,s,o); if(lane>=o) s+=u; }
  if(lane==31) wsum[w]=s;
  __syncthreads();
  if(w==0){
    int x = (lane<8)? wsum[lane] : 0;
    #pragma unroll
    for(int o=1;o<8;o<<=1){ int u=__shfl_up_sync(0xffffffffu,x,o); if(lane>=o) x+=u; }
    if(lane<8) wsum[lane]=x;
  }
  __syncthreads();
  g_poff[t] = s - v + (w ? wsum[w-1] : 0);
}
__global__ void scan3_kernel(){
  int b = blockIdx.x, t = threadIdx.x;
  int i = b*256 + t;
  int r = g_rowptr[i] + g_poff[b];
  g_rowptr[i] = r;
  g_cursor[i] = r;
  if(i == 0) g_rowptr[NN] = NE;
}
__global__ void fill_kernel(const int* __restrict__ src, const int* __restrict__ dst){
  int e = blockIdx.x*blockDim.x + threadIdx.x;
  if(e >= NE) return;
  int s = src[e], d = dst[e];
  int pos = atomicAdd(&g_cursor[d], 1);
  g_edge[pos] = make_float2(__int_as_float(s), g_dis[s]*g_dis[d]);
}

// ================= aggregation (warp per node, gather-only) =================
__global__ void agg64_kernel(const float* __restrict__ hin, float* __restrict__ out){
  int gw = (blockIdx.x*blockDim.x + threadIdx.x) >> 5;
  int lane = threadIdx.x & 31;
  if(gw >= NN) return;
  float2 a = *((const float2*)(hin + (size_t)gw*INDIM) + lane);
  float sn = g_selfn[gw];
  a.x *= sn; a.y *= sn;
  int beg = g_rowptr[gw], end = g_rowptr[gw+1];
  for(int e = beg; e < end; e++){
    float2 ed = g_edge[e];
    int s = __float_as_int(ed.x);
    float w = ed.y;
    float2 v = *((const float2*)(hin + (size_t)s*INDIM) + lane);
    a.x += w*v.x; a.y += w*v.y;
  }
  *((float2*)(out + (size_t)gw*INDIM) + lane) = a;
}
__global__ void agg128_kernel(const float* __restrict__ hin, float* __restrict__ out){
  int gw = (blockIdx.x*blockDim.x + threadIdx.x) >> 5;
  int lane = threadIdx.x & 31;
  if(gw >= NN) return;
  float4 a = *((const float4*)(hin + (size_t)gw*HIDD) + lane);
  float sn = g_selfn[gw];
  a.x *= sn; a.y *= sn; a.z *= sn; a.w *= sn;
  int beg = g_rowptr[gw], end = g_rowptr[gw+1];
  for(int e = beg; e < end; e++){
    float2 ed = g_edge[e];
    int s = __float_as_int(ed.x);
    float w = ed.y;
    float4 v = *((const float4*)(hin + (size_t)s*HIDD) + lane);
    a.x += w*v.x; a.y += w*v.y; a.z += w*v.z; a.w += w*v.w;
  }
  *((float4*)(out + (size_t)gw*HIDD) + lane) = a;
}

// ================= tf32 mma.sync GEMM =================
// C[128 x 128 tile] = A[M,KK] x Bop (+bias, optional BN+ReLU), fp32 accumulate.
// BT=1: B given as [Ncols, KK] row-major (x @ W^T) -> smem [n][k], stride SA.
// BT=0: B given as [KK, Ndt]  (h @ W)              -> smem [k][n], stride 132 (no transpose).
// All staging uses uint4 STS.128 (conflict-free); fragment LDS patterns bank-verified.
template<int BT, int EPI, int KK>
__global__ __launch_bounds__(256)
void gemm_mma_kernel(const float* __restrict__ A, const float* __restrict__ B,
                     const float* __restrict__ bias,
                     const float* __restrict__ bng, const float* __restrict__ bnb,
                     const float* __restrict__ bnm, const float* __restrict__ bnv,
                     float* __restrict__ C, int Ndt)
{
  constexpr int SA = KK + 4;      // A stride; also B stride for BT=1 (KK=128 -> 132)
  constexpr int SBN = 132;        // B stride for BT=0 [k][n]
  extern __shared__ uint32_t sm[];
  uint32_t* As = sm;                      // [128][SA]
  uint32_t* Bs = sm + 128*SA;             // BT1: [128][SA]; BT0: [KK][SBN]
  const int tid = threadIdx.x;
  const int lane = tid & 31, wid = tid >> 5;
  const int row0 = blockIdx.x * 128;
  const int col0 = blockIdx.y * 128;

  constexpr int KQ = KK/4;
  for(int idx = tid; idx < 128*KQ; idx += 256){
    int r = idx / KQ, q = idx % KQ;
    float4 v = *(const float4*)(A + (size_t)(row0 + r)*KK + q*4);
    *(uint4*)(As + r*SA + q*4) = q4(v);
  }
  if(BT){
    for(int idx = tid; idx < 128*KQ; idx += 256){
      int r = idx / KQ, q = idx % KQ;
      float4 v = *(const float4*)(B + (size_t)(col0 + r)*KK + q*4);
      *(uint4*)(Bs + r*SA + q*4) = q4(v);
    }
  } else {
    for(int idx = tid; idx < KK*32; idx += 256){
      int k = idx >> 5, n4 = idx & 31;
      float4 v = *(const float4*)(B + (size_t)k*Ndt + col0 + n4*4);
      *(uint4*)(Bs + k*SBN + n4*4) = q4(v);
    }
  }
  __syncthreads();

  const int m0 = (wid >> 1) * 32;     // warp tile: 32 rows x 64 cols
  const int n0 = (wid & 1) * 64;
  const int g  = lane >> 2;
  const int t4 = lane & 3;

  float acc[2][8][4];
  #pragma unroll
  for(int i=0;i<2;i++)
    #pragma unroll
    for(int j=0;j<8;j++)
      #pragma unroll
      for(int q=0;q<4;q++) acc[i][j][q]=0.f;

  const uint32_t* Aw0 = As + (m0 + g)*SA + t4;
  const uint32_t* Aw1 = As + (m0 + 16 + g)*SA + t4;
  const uint32_t* Bw1 = Bs + (n0 + g)*SA + t4;   // BT=1 path
  const uint32_t* Bw0 = Bs + t4*SBN + n0 + g;    // BT=0 path

  #pragma unroll 1
  for(int ks = 0; ks < KK/8; ks++){
    const int k0 = ks*8;
    uint32_t af[2][4];
    af[0][0] = Aw0[k0];       af[0][1] = Aw0[8*SA + k0];
    af[0][2] = Aw0[k0 + 4];   af[0][3] = Aw0[8*SA + k0 + 4];
    af[1][0] = Aw1[k0];       af[1][1] = Aw1[8*SA + k0];
    af[1][2] = Aw1[k0 + 4];   af[1][3] = Aw1[8*SA + k0 + 4];
    #pragma unroll
    for(int nj = 0; nj < 8; nj++){
      uint32_t b0, b1;
      if(BT){
        b0 = Bw1[nj*8*SA + k0];
        b1 = Bw1[nj*8*SA + k0 + 4];
      } else {
        b0 = Bw0[k0*SBN + nj*8];
        b1 = Bw0[(k0+4)*SBN + nj*8];
      }
      mma_tf32(acc[0][nj][0], acc[0][nj][1], acc[0][nj][2], acc[0][nj][3],
               af[0][0], af[0][1], af[0][2], af[0][3], b0, b1);
      mma_tf32(acc[1][nj][0], acc[1][nj][1], acc[1][nj][2], acc[1][nj][3],
               af[1][0], af[1][1], af[1][2], af[1][3], b0, b1);
    }
  }

  #pragma unroll
  for(int mi = 0; mi < 2; mi++){
    #pragma unroll
    for(int nj = 0; nj < 8; nj++){
      int c = col0 + n0 + nj*8 + t4*2;
      float s0, s1;
      if(EPI){
        s0 = bng[c  ]*rsqrtf(bnv[c  ] + BN_EPS);
        s1 = bng[c+1]*rsqrtf(bnv[c+1] + BN_EPS);
      }
      #pragma unroll
      for(int h = 0; h < 2; h++){
        int r = row0 + m0 + mi*16 + g + h*8;
        float v0 = acc[mi][nj][h*2+0] + bias[c];
        float v1 = acc[mi][nj][h*2+1] + bias[c+1];
        if(EPI){
          v0 = fmaxf((v0 - bnm[c  ])*s0 + bnb[c  ], 0.f);
          v1 = fmaxf((v1 - bnm[c+1])*s1 + bnb[c+1], 0.f);
        }
        *(float2*)(C + (size_t)r*Ndt + c) = make_float2(v0, v1);
      }
    }
  }
}

// ================= attention via tf32 mma: CTA per (graph, head, half) ===========
// smem floats: Ks[512][36] | Vs[512][40] | S[32][516] | QP(Q tile / PV partials) | Sinv[32]
#define KSTR 36
#define VSTR 40
#define SSTR 516
#define PSTR 36
#define KS_OFF 0
#define VS_OFF (512*KSTR)                   // 18432
#define S_OFF  (VS_OFF + 512*VSTR)          // 38912
#define QP_OFF (S_OFF + 32*SSTR)            // 55424
#define SINV_OFF (QP_OFF + 2*32*PSTR)       // 57728
#define ATTN_FLOATS (SINV_OFF + 32)         // 57760

__global__ __launch_bounds__(256)
void attn_mma_kernel(const float* __restrict__ qkv, float* __restrict__ out){
  extern __shared__ float smf[];
  float* S    = smf + S_OFF;
  float* QP   = smf + QP_OFF;
  float* Sinv = smf + SINV_OFF;
  uint32_t* Ku = (uint32_t*)(smf + KS_OFF);
  uint32_t* Vu = (uint32_t*)(smf + VS_OFF);
  uint32_t* Su = (uint32_t*)S;
  uint32_t* Qu = (uint32_t*)QP;

  int g    = blockIdx.x >> 3;
  int hd   = (blockIdx.x >> 1) & 3;
  int half = blockIdx.x & 1;
  int n0 = g*PN;
  int t = threadIdx.x;
  int lane = t & 31, warp = t >> 5;
  int gq = lane >> 2, t4 = lane & 3;
  const float scale = 0.17677669529663687f;  // 1/sqrt(32)

  // stage K,V tf32-rounded (uint4 stores)
  for(int idx = t; idx < PN*8; idx += 256){
    int r = idx >> 3, d4 = (idx & 7)*4;
    const float* row = qkv + (size_t)(n0 + r)*384 + hd*32;
    *(uint4*)(Ku + r*KSTR + d4) = q4(*(const float4*)(row + 128 + d4));
    *(uint4*)(Vu + r*VSTR + d4) = q4(*(const float4*)(row + 256 + d4));
  }
  __syncthreads();

  for(int qi8 = 0; qi8 < 8; qi8++){
    int qt = half*8 + qi8;
    // stage Q tile, scale folded in
    for(int idx = t; idx < 32*8; idx += 256){
      int r = idx >> 3, d4 = (idx & 7)*4;
      float4 qv = *(const float4*)(qkv + (size_t)(n0 + qt*32 + r)*384 + hd*32 + d4);
      qv.x *= scale; qv.y *= scale; qv.z *= scale; qv.w *= scale;
      *(uint4*)(Qu + r*PSTR + d4) = q4(qv);
    }
    __syncthreads();

    // Phase A: S[0..32][warp*64 .. +64] = Qs K^T (scale already folded)
    {
      float c[2][8][4];
      #pragma unroll
      for(int i=0;i<2;i++)
        #pragma unroll
        for(int j=0;j<8;j++)
          #pragma unroll
          for(int q=0;q<4;q++) c[i][j][q]=0.f;

      #pragma unroll 1
      for(int ks = 0; ks < 4; ks++){
        int k0 = ks*8;
        uint32_t a[2][4];
        #pragma unroll
        for(int mi=0;mi<2;mi++){
          const uint32_t* qb = Qu + (mi*16+gq)*PSTR + k0 + t4;
          a[mi][0]=qb[0]; a[mi][1]=qb[8*PSTR]; a[mi][2]=qb[4]; a[mi][3]=qb[8*PSTR+4];
        }
        #pragma unroll
        for(int nj=0;nj<8;nj++){
          const uint32_t* kb = Ku + (warp*64+nj*8+gq)*KSTR + k0 + t4;
          uint32_t b0 = kb[0], b1 = kb[4];
          mma_tf32(c[0][nj][0],c[0][nj][1],c[0][nj][2],c[0][nj][3],
                   a[0][0],a[0][1],a[0][2],a[0][3], b0,b1);
          mma_tf32(c[1][nj][0],c[1][nj][1],c[1][nj][2],c[1][nj][3],
                   a[1][0],a[1][1],a[1][2],a[1][3], b0,b1);
        }
      }
      #pragma unroll
      for(int mi=0;mi<2;mi++)
        #pragma unroll
        for(int nj=0;nj<8;nj++){
          float* sp = S + (mi*16+gq)*SSTR + warp*64 + nj*8 + t4*2;
          *(float2*)(sp)          = make_float2(c[mi][nj][0], c[mi][nj][1]);
          *(float2*)(sp + 8*SSTR) = make_float2(c[mi][nj][2], c[mi][nj][3]);
        }
    }
    __syncthreads();

    // Phase B: single-pass exp + sum (no max-subtract; scores are O(1) here);
    // store unnormalized exp tf32-rounded; normalization deferred to output.
    for(int rr = 0; rr < 4; rr++){
      int r = warp*4 + rr;
      float sum = 0.f;
      for(int j = lane; j < 512; j += 32){
        float e = __expf(S[r*SSTR + j]);
        S[r*SSTR + j] = __uint_as_float(f2tf32(e));
        sum += e;
      }
      #pragma unroll
      for(int o=16;o;o>>=1) sum += __shfl_xor_sync(0xffffffffu, sum, o);
      if(lane == 0) Sinv[r] = 1.f/sum;
    }
    __syncthreads();

    // Phase C: O_unnorm = E V  (warps: 2q x 2n x 2k; partials over k-chunks)
    {
      int wq = warp & 1, wn = (warp >> 1) & 1, wk = warp >> 2;
      float c[2][4] = {};
      #pragma unroll 2
      for(int ks = 0; ks < 32; ks++){
        int k0 = wk*256 + ks*8;
        const uint32_t* pb = Su + (wq*16+gq)*SSTR + k0 + t4;
        uint32_t a0 = pb[0], a1 = pb[8*SSTR], a2 = pb[4], a3 = pb[8*SSTR+4];
        #pragma unroll
        for(int nj=0;nj<2;nj++){
          const uint32_t* vb = Vu + (k0+t4)*VSTR + wn*16 + nj*8 + gq;
          uint32_t b0 = vb[0], b1 = vb[4*VSTR];
          mma_tf32(c[nj][0],c[nj][1],c[nj][2],c[nj][3], a0,a1,a2,a3, b0,b1);
        }
      }
      float* part = QP + wk*32*PSTR;
      #pragma unroll
      for(int nj=0;nj<2;nj++){
        float* pp = part + (wq*16+gq)*PSTR + wn*16 + nj*8 + t4*2;
        *(float2*)(pp)          = make_float2(c[nj][0], c[nj][1]);
        *(float2*)(pp + 8*PSTR) = make_float2(c[nj][2], c[nj][3]);
      }
    }
    __syncthreads();

    // reduce 2 k-partials, normalize, write out
    {
      int q = t >> 3, dq = (t & 7)*4;
      float inv = Sinv[q];
      float4 p0 = *(float4*)(QP + q*PSTR + dq);
      float4 p1 = *(float4*)(QP + 32*PSTR + q*PSTR + dq);
      float4 o = make_float4((p0.x+p1.x)*inv, (p0.y+p1.y)*inv,
                             (p0.z+p1.z)*inv, (p0.w+p1.w)*inv);
      *(float4*)(out + (size_t)(n0 + qt*32 + q)*HIDD + hd*32 + dq) = o;
    }
    __syncthreads();
  }
}

// ================= mean pool =================
__global__ void pool_kernel(const float* __restrict__ fin, float* __restrict__ emb){
  int g = blockIdx.x, d = threadIdx.x;
  float s = 0.f;
  const float* base = fin + (size_t)g*PN*HIDD + d;
  for(int i = 0; i < PN; i++) s += base[(size_t)i*HIDD];
  emb[g*HIDD + d] = s * (1.0f/PN);
}

// ================= launch =================
extern "C" void kernel_launch(void* const* d_in, const int* in_sizes, int n_in,
                              void* d_out, int out_size) {
  const float* x   = (const float*)d_in[0];
  const float* W0  = (const float*)d_in[1];
  const float* b0  = (const float*)d_in[2];
  const float* Wh  = (const float*)d_in[3];
  const float* bh  = (const float*)d_in[4];
  const float* bng = (const float*)d_in[5];
  const float* bnb = (const float*)d_in[6];
  const float* bnm = (const float*)d_in[7];
  const float* bnv = (const float*)d_in[8];
  const float* aiw = (const float*)d_in[9];
  const float* aib = (const float*)d_in[10];
  const float* aow = (const float*)d_in[11];
  const float* aob = (const float*)d_in[12];
  const int*  eidx = (const int*)d_in[13];

  float* out_final = (float*)d_out;
  float* out_emb   = out_final + (size_t)NN*HIDD;

  const int* src = eidx;
  const int* dst = eidx + NE;

  float *p_h, *p_agg, *p_qkv, *p_attno;
  int* p_count;
  cudaGetSymbolAddress((void**)&p_h,     g_h);
  cudaGetSymbolAddress((void**)&p_agg,   g_agg);
  cudaGetSymbolAddress((void**)&p_qkv,   g_qkv);
  cudaGetSymbolAddress((void**)&p_attno, g_attno);
  cudaGetSymbolAddress((void**)&p_count, g_count);

  const int GEMM_SMEM64  = (128*68 + 64*132)*4;   // 68608
  const int GEMM_SMEM128 = 2*128*132*4;           // 135168
  const int ATTN_SMEM = ATTN_FLOATS*4;            // 231040
  cudaFuncSetAttribute(gemm_mma_kernel<0,1,64>,  cudaFuncAttributeMaxDynamicSharedMemorySize, GEMM_SMEM64);
  cudaFuncSetAttribute(gemm_mma_kernel<0,1,128>, cudaFuncAttributeMaxDynamicSharedMemorySize, GEMM_SMEM128);
  cudaFuncSetAttribute(gemm_mma_kernel<1,0,128>, cudaFuncAttributeMaxDynamicSharedMemorySize, GEMM_SMEM128);
  cudaFuncSetAttribute(attn_mma_kernel,          cudaFuncAttributeMaxDynamicSharedMemorySize, ATTN_SMEM);

  // CSR build
  cudaMemsetAsync(p_count, 0, NN*sizeof(int));
  count_kernel<<<NE/256, 256>>>(dst);
  scan1_kernel<<<256, 256>>>();
  scan2_kernel<<<1, 256>>>();
  scan3_kernel<<<256, 256>>>();
  fill_kernel<<<NE/256, 256>>>(src, dst);

  // layer 0: aggregate in input space (64-d), then tf32 GEMM + BN + ReLU
  agg64_kernel<<<NN*32/256, 256>>>(x, p_agg);
  gemm_mma_kernel<0,1,64><<<dim3(512,1), 256, GEMM_SMEM64>>>(
      p_agg, W0, b0, bng, bnb, bnm, bnv, p_h, 128);

  // layers 1..3
  for(int l = 0; l < 3; l++){
    agg128_kernel<<<NN*32/256, 256>>>(p_h, p_agg);
    gemm_mma_kernel<0,1,128><<<dim3(512,1), 256, GEMM_SMEM128>>>(
        p_agg, Wh + (size_t)l*HIDD*HIDD, bh + l*HIDD,
        bng + (l+1)*HIDD, bnb + (l+1)*HIDD, bnm + (l+1)*HIDD, bnv + (l+1)*HIDD,
        p_h, 128);
  }

  // qkv projection: [N,128] @ attn_in_w^T -> [N,384]
  gemm_mma_kernel<1,0,128><<<dim3(512,3), 256, GEMM_SMEM128>>>(
      p_h, aiw, aib, nullptr, nullptr, nullptr, nullptr, p_qkv, 384);

  // attention per (graph, head, half) — tensor cores
  attn_mma_kernel<<<NG*4*2, 256, ATTN_SMEM>>>(p_qkv, p_attno);

  // output projection -> final
  gemm_mma_kernel<1,0,128><<<dim3(512,1), 256, GEMM_SMEM128>>>(
      p_attno, aow, aob, nullptr, nullptr, nullptr, nullptr, out_final, 128);

  // mean pool -> graph_emb
  pool_kernel<<<NG, HIDD>>>(out_final, out_emb);
}

// round 9
// speedup vs baseline: 3.3461x; 1.2085x over previous
#include <cuda_runtime.h>
#include <cstdint>

#define NN 65536
#define NE (NN*16)
#define NG 128
#define PN 512
#define HIDD 128
#define INDIM 64
#define BN_EPS 1e-5f

__device__ __forceinline__ uint32_t f2tf32(float f){
  uint32_t u; asm("cvt.rna.tf32.f32 %0, %1;" : "=r"(u) : "f"(f)); return u;
}
__device__ __forceinline__ void mma_tf32(float& c0, float& c1, float& c2, float& c3,
                                         uint32_t a0, uint32_t a1, uint32_t a2, uint32_t a3,
                                         uint32_t b0, uint32_t b1){
  asm volatile("mma.sync.aligned.m16n8k8.row.col.f32.tf32.tf32.f32 "
               "{%0,%1,%2,%3}, {%4,%5,%6,%7}, {%8,%9}, {%0,%1,%2,%3};"
               : "+f"(c0), "+f"(c1), "+f"(c2), "+f"(c3)
               : "r"(a0), "r"(a1), "r"(a2), "r"(a3), "r"(b0), "r"(b1));
}
__device__ __forceinline__ uint4 q4(float4 v){
  return make_uint4(f2tf32(v.x), f2tf32(v.y), f2tf32(v.z), f2tf32(v.w));
}

// ================= scratch =================
__device__ int    g_count[NN];
__device__ int    g_rowptr[NN+1];
__device__ int    g_cursor[NN];
__device__ int    g_part[256];
__device__ int    g_poff[256];
__device__ float2 g_edge[NE];     // (src bits, weight)
__device__ float  g_dis[NN];
__device__ float  g_selfn[NN];
__device__ float  g_h[(size_t)NN*HIDD];
__device__ float  g_agg[(size_t)NN*HIDD];
__device__ float  g_qkv[(size_t)NN*3*HIDD];
__device__ float  g_attno[(size_t)NN*HIDD];

// ================= CSR build =================
__global__ void count_kernel(const int* __restrict__ dst){
  int e = blockIdx.x*blockDim.x + threadIdx.x;
  if(e < NE) atomicAdd(&g_count[dst[e]], 1);
}
__global__ void scan1_kernel(){
  __shared__ int wsum[8];
  int b = blockIdx.x, t = threadIdx.x;
  int i = b*256 + t;
  int c = g_count[i];
  float dis = rsqrtf((float)(c + 1));
  g_dis[i] = dis;
  g_selfn[i] = dis*dis;
  int lane = t & 31, w = t >> 5;
  int v = c;
  #pragma unroll
  for(int o=1;o<32;o<<=1){ int u=__shfl_up_sync(0xffffffffu,v,o); if(lane>=o) v+=u; }
  if(lane==31) wsum[w]=v;
  __syncthreads();
  if(w==0){
    int s = (lane<8)? wsum[lane] : 0;
    #pragma unroll
    for(int o=1;o<8;o<<=1){ int u=__shfl_up_sync(0xffffffffu,s,o); if(lane>=o) s+=u; }
    if(lane<8) wsum[lane]=s;
  }
  __syncthreads();
  int excl = v - c + (w ? wsum[w-1] : 0);
  g_rowptr[i] = excl;
  if(t==255) g_part[b] = excl + c;
}
__global__ void scan2_kernel(){
  __shared__ int wsum[8];
  int t = threadIdx.x;
  int v = g_part[t];
  int lane = t & 31, w = t >> 5;
  int s = v;
  #pragma unroll
  for(int o=1;o<32;o<<=1){ int u=__shfl_up_sync(0xffffffffu,s,o); if(lane>=o) s+=u; }
  if(lane==31) wsum[w]=s;
  __syncthreads();
  if(w==0){
    int x = (lane<8)? wsum[lane] : 0;
    #pragma unroll
    for(int o=1;o<8;o<<=1){ int u=__shfl_up_sync(0xffffffffu,x,o); if(lane>=o) x+=u; }
    if(lane<8) wsum[lane]=x;
  }
  __syncthreads();
  g_poff[t] = s - v + (w ? wsum[w-1] : 0);
}
__global__ void scan3_kernel(){
  int b = blockIdx.x, t = threadIdx.x;
  int i = b*256 + t;
  int r = g_rowptr[i] + g_poff[b];
  g_rowptr[i] = r;
  g_cursor[i] = r;
  if(i == 0) g_rowptr[NN] = NE;
}
__global__ void fill_kernel(const int* __restrict__ src, const int* __restrict__ dst){
  int e = blockIdx.x*blockDim.x + threadIdx.x;
  if(e >= NE) return;
  int s = src[e], d = dst[e];
  int pos = atomicAdd(&g_cursor[d], 1);
  g_edge[pos] = make_float2(__int_as_float(s), g_dis[s]*g_dis[d]);
}

// ======== aggregation (warp per node; edge records prefetched + shfl-broadcast) ========
__global__ void agg64_kernel(const float* __restrict__ hin, float* __restrict__ out){
  int gw = (blockIdx.x*blockDim.x + threadIdx.x) >> 5;
  int lane = threadIdx.x & 31;
  if(gw >= NN) return;
  float2 a = *((const float2*)(hin + (size_t)gw*INDIM) + lane);
  float sn = g_selfn[gw];
  a.x *= sn; a.y *= sn;
  int beg = g_rowptr[gw], end = g_rowptr[gw+1];
  for(int b = beg; b < end; b += 32){
    int m = min(32, end - b);
    float2 myed = make_float2(0.f, 0.f);
    if(lane < m) myed = g_edge[b + lane];
    #pragma unroll 2
    for(int i = 0; i < m; i++){
      int   s = __shfl_sync(0xffffffffu, __float_as_int(myed.x), i);
      float w = __shfl_sync(0xffffffffu, myed.y, i);
      float2 v = *((const float2*)(hin + (size_t)s*INDIM) + lane);
      a.x += w*v.x; a.y += w*v.y;
    }
  }
  *((float2*)(out + (size_t)gw*INDIM) + lane) = a;
}
__global__ void agg128_kernel(const float* __restrict__ hin, float* __restrict__ out){
  int gw = (blockIdx.x*blockDim.x + threadIdx.x) >> 5;
  int lane = threadIdx.x & 31;
  if(gw >= NN) return;
  float4 a = *((const float4*)(hin + (size_t)gw*HIDD) + lane);
  float sn = g_selfn[gw];
  a.x *= sn; a.y *= sn; a.z *= sn; a.w *= sn;
  int beg = g_rowptr[gw], end = g_rowptr[gw+1];
  for(int b = beg; b < end; b += 32){
    int m = min(32, end - b);
    float2 myed = make_float2(0.f, 0.f);
    if(lane < m) myed = g_edge[b + lane];
    #pragma unroll 2
    for(int i = 0; i < m; i++){
      int   s = __shfl_sync(0xffffffffu, __float_as_int(myed.x), i);
      float w = __shfl_sync(0xffffffffu, myed.y, i);
      float4 v = *((const float4*)(hin + (size_t)s*HIDD) + lane);
      a.x += w*v.x; a.y += w*v.y; a.z += w*v.z; a.w += w*v.w;
    }
  }
  *((float4*)(out + (size_t)gw*HIDD) + lane) = a;
}

// ================= tf32 mma.sync GEMM (K-chunked staging, 2 CTAs/SM) =================
// C[128 x 128 tile] = A[M,KK] x Bop (+bias, optional BN+ReLU), fp32 accumulate.
// K staged in 64-wide chunks: smem ~70KB -> 2 CTAs/SM (cross-CTA stage/compute overlap).
// BT=1: B given as [Ncols, KK] row-major -> smem [n][kchunk], stride 68.
// BT=0: B given as [KK, Ndt]            -> smem [kchunk][n], stride 132 (no transpose).
template<int BT, int EPI, int KK>
__global__ __launch_bounds__(256, 2)
void gemm_mma_kernel(const float* __restrict__ A, const float* __restrict__ B,
                     const float* __restrict__ bias,
                     const float* __restrict__ bng, const float* __restrict__ bnb,
                     const float* __restrict__ bnm, const float* __restrict__ bnv,
                     float* __restrict__ C, int Ndt)
{
  constexpr int CK  = 64;         // K chunk
  constexpr int NCH = KK / CK;
  constexpr int SA  = CK + 4;     // 68: A chunk stride, and B stride for BT=1
  constexpr int SBN = 132;        // B stride for BT=0 [k][n]
  extern __shared__ uint32_t sm[];
  uint32_t* As = sm;              // [128][68]
  uint32_t* Bs = sm + 128*SA;     // BT1: [128][68]; BT0: [64][132]
  const int tid = threadIdx.x;
  const int lane = tid & 31, wid = tid >> 5;
  const int row0 = blockIdx.x * 128;
  const int col0 = blockIdx.y * 128;

  const int m0 = (wid >> 1) * 32;     // warp tile: 32 rows x 64 cols
  const int n0 = (wid & 1) * 64;
  const int g  = lane >> 2;
  const int t4 = lane & 3;

  float acc[2][8][4];
  #pragma unroll
  for(int i=0;i<2;i++)
    #pragma unroll
    for(int j=0;j<8;j++)
      #pragma unroll
      for(int q=0;q<4;q++) acc[i][j][q]=0.f;

  #pragma unroll 1
  for(int ch = 0; ch < NCH; ch++){
    const int kbase = ch*CK;
    // stage A chunk: rows 128 x 64 k
    for(int idx = tid; idx < 128*16; idx += 256){
      int r = idx >> 4, q = idx & 15;
      float4 v = *(const float4*)(A + (size_t)(row0 + r)*KK + kbase + q*4);
      *(uint4*)(As + r*SA + q*4) = q4(v);
    }
    if(BT){
      for(int idx = tid; idx < 128*16; idx += 256){
        int r = idx >> 4, q = idx & 15;
        float4 v = *(const float4*)(B + (size_t)(col0 + r)*KK + kbase + q*4);
        *(uint4*)(Bs + r*SA + q*4) = q4(v);
      }
    } else {
      for(int idx = tid; idx < CK*32; idx += 256){
        int k = idx >> 5, n4 = idx & 31;
        float4 v = *(const float4*)(B + (size_t)(kbase + k)*Ndt + col0 + n4*4);
        *(uint4*)(Bs + k*SBN + n4*4) = q4(v);
      }
    }
    __syncthreads();

    const uint32_t* Aw0 = As + (m0 + g)*SA + t4;
    const uint32_t* Aw1 = As + (m0 + 16 + g)*SA + t4;
    const uint32_t* Bw1 = Bs + (n0 + g)*SA + t4;
    const uint32_t* Bw0 = Bs + t4*SBN + n0 + g;

    #pragma unroll 1
    for(int ks = 0; ks < CK/8; ks++){
      const int k0 = ks*8;
      uint32_t af[2][4];
      af[0][0] = Aw0[k0];       af[0][1] = Aw0[8*SA + k0];
      af[0][2] = Aw0[k0 + 4];   af[0][3] = Aw0[8*SA + k0 + 4];
      af[1][0] = Aw1[k0];       af[1][1] = Aw1[8*SA + k0];
      af[1][2] = Aw1[k0 + 4];   af[1][3] = Aw1[8*SA + k0 + 4];
      #pragma unroll
      for(int nj = 0; nj < 8; nj++){
        uint32_t b0, b1;
        if(BT){
          b0 = Bw1[nj*8*SA + k0];
          b1 = Bw1[nj*8*SA + k0 + 4];
        } else {
          b0 = Bw0[k0*SBN + nj*8];
          b1 = Bw0[(k0+4)*SBN + nj*8];
        }
        mma_tf32(acc[0][nj][0], acc[0][nj][1], acc[0][nj][2], acc[0][nj][3],
                 af[0][0], af[0][1], af[0][2], af[0][3], b0, b1);
        mma_tf32(acc[1][nj][0], acc[1][nj][1], acc[1][nj][2], acc[1][nj][3],
                 af[1][0], af[1][1], af[1][2], af[1][3], b0, b1);
      }
    }
    if(ch + 1 < NCH) __syncthreads();
  }

  #pragma unroll
  for(int mi = 0; mi < 2; mi++){
    #pragma unroll
    for(int nj = 0; nj < 8; nj++){
      int c = col0 + n0 + nj*8 + t4*2;
      float s0, s1;
      if(EPI){
        s0 = bng[c  ]*rsqrtf(bnv[c  ] + BN_EPS);
        s1 = bng[c+1]*rsqrtf(bnv[c+1] + BN_EPS);
      }
      #pragma unroll
      for(int h = 0; h < 2; h++){
        int r = row0 + m0 + mi*16 + g + h*8;
        float v0 = acc[mi][nj][h*2+0] + bias[c];
        float v1 = acc[mi][nj][h*2+1] + bias[c+1];
        if(EPI){
          v0 = fmaxf((v0 - bnm[c  ])*s0 + bnb[c  ], 0.f);
          v1 = fmaxf((v1 - bnm[c+1])*s1 + bnb[c+1], 0.f);
        }
        *(float2*)(C + (size_t)r*Ndt + c) = make_float2(v0, v1);
      }
    }
  }
}

// ================= attention via tf32 mma: CTA per (graph, head, half) ===========
#define KSTR 36
#define VSTR 40
#define SSTR 516
#define PSTR 36
#define KS_OFF 0
#define VS_OFF (512*KSTR)
#define S_OFF  (VS_OFF + 512*VSTR)
#define QP_OFF (S_OFF + 32*SSTR)
#define SINV_OFF (QP_OFF + 2*32*PSTR)
#define ATTN_FLOATS (SINV_OFF + 32)

__global__ __launch_bounds__(256)
void attn_mma_kernel(const float* __restrict__ qkv, float* __restrict__ out){
  extern __shared__ float smf[];
  float* S    = smf + S_OFF;
  float* QP   = smf + QP_OFF;
  float* Sinv = smf + SINV_OFF;
  uint32_t* Ku = (uint32_t*)(smf + KS_OFF);
  uint32_t* Vu = (uint32_t*)(smf + VS_OFF);
  uint32_t* Su = (uint32_t*)S;
  uint32_t* Qu = (uint32_t*)QP;

  int g    = blockIdx.x >> 3;
  int hd   = (blockIdx.x >> 1) & 3;
  int half = blockIdx.x & 1;
  int n0 = g*PN;
  int t = threadIdx.x;
  int lane = t & 31, warp = t >> 5;
  int gq = lane >> 2, t4 = lane & 3;
  const float scale = 0.17677669529663687f;

  for(int idx = t; idx < PN*8; idx += 256){
    int r = idx >> 3, d4 = (idx & 7)*4;
    const float* row = qkv + (size_t)(n0 + r)*384 + hd*32;
    *(uint4*)(Ku + r*KSTR + d4) = q4(*(const float4*)(row + 128 + d4));
    *(uint4*)(Vu + r*VSTR + d4) = q4(*(const float4*)(row + 256 + d4));
  }
  __syncthreads();

  for(int qi8 = 0; qi8 < 8; qi8++){
    int qt = half*8 + qi8;
    for(int idx = t; idx < 32*8; idx += 256){
      int r = idx >> 3, d4 = (idx & 7)*4;
      float4 qv = *(const float4*)(qkv + (size_t)(n0 + qt*32 + r)*384 + hd*32 + d4);
      qv.x *= scale; qv.y *= scale; qv.z *= scale; qv.w *= scale;
      *(uint4*)(Qu + r*PSTR + d4) = q4(qv);
    }
    __syncthreads();

    // Phase A: S = Qs K^T
    {
      float c[2][8][4];
      #pragma unroll
      for(int i=0;i<2;i++)
        #pragma unroll
        for(int j=0;j<8;j++)
          #pragma unroll
          for(int q=0;q<4;q++) c[i][j][q]=0.f;

      #pragma unroll 1
      for(int ks = 0; ks < 4; ks++){
        int k0 = ks*8;
        uint32_t a[2][4];
        #pragma unroll
        for(int mi=0;mi<2;mi++){
          const uint32_t* qb = Qu + (mi*16+gq)*PSTR + k0 + t4;
          a[mi][0]=qb[0]; a[mi][1]=qb[8*PSTR]; a[mi][2]=qb[4]; a[mi][3]=qb[8*PSTR+4];
        }
        #pragma unroll
        for(int nj=0;nj<8;nj++){
          const uint32_t* kb = Ku + (warp*64+nj*8+gq)*KSTR + k0 + t4;
          uint32_t b0 = kb[0], b1 = kb[4];
          mma_tf32(c[0][nj][0],c[0][nj][1],c[0][nj][2],c[0][nj][3],
                   a[0][0],a[0][1],a[0][2],a[0][3], b0,b1);
          mma_tf32(c[1][nj][0],c[1][nj][1],c[1][nj][2],c[1][nj][3],
                   a[1][0],a[1][1],a[1][2],a[1][3], b0,b1);
        }
      }
      #pragma unroll
      for(int mi=0;mi<2;mi++)
        #pragma unroll
        for(int nj=0;nj<8;nj++){
          float* sp = S + (mi*16+gq)*SSTR + warp*64 + nj*8 + t4*2;
          *(float2*)(sp)          = make_float2(c[mi][nj][0], c[mi][nj][1]);
          *(float2*)(sp + 8*SSTR) = make_float2(c[mi][nj][2], c[mi][nj][3]);
        }
    }
    __syncthreads();

    // Phase B: single-pass exp + sum; normalization deferred
    for(int rr = 0; rr < 4; rr++){
      int r = warp*4 + rr;
      float sum = 0.f;
      for(int j = lane; j < 512; j += 32){
        float e = __expf(S[r*SSTR + j]);
        S[r*SSTR + j] = __uint_as_float(f2tf32(e));
        sum += e;
      }
      #pragma unroll
      for(int o=16;o;o>>=1) sum += __shfl_xor_sync(0xffffffffu, sum, o);
      if(lane == 0) Sinv[r] = 1.f/sum;
    }
    __syncthreads();

    // Phase C: O_unnorm = E V
    {
      int wq = warp & 1, wn = (warp >> 1) & 1, wk = warp >> 2;
      float c[2][4] = {};
      #pragma unroll 2
      for(int ks = 0; ks < 32; ks++){
        int k0 = wk*256 + ks*8;
        const uint32_t* pb = Su + (wq*16+gq)*SSTR + k0 + t4;
        uint32_t a0 = pb[0], a1 = pb[8*SSTR], a2 = pb[4], a3 = pb[8*SSTR+4];
        #pragma unroll
        for(int nj=0;nj<2;nj++){
          const uint32_t* vb = Vu + (k0+t4)*VSTR + wn*16 + nj*8 + gq;
          uint32_t b0 = vb[0], b1 = vb[4*VSTR];
          mma_tf32(c[nj][0],c[nj][1],c[nj][2],c[nj][3], a0,a1,a2,a3, b0,b1);
        }
      }
      float* part = QP + wk*32*PSTR;
      #pragma unroll
      for(int nj=0;nj<2;nj++){
        float* pp = part + (wq*16+gq)*PSTR + wn*16 + nj*8 + t4*2;
        *(float2*)(pp)          = make_float2(c[nj][0], c[nj][1]);
        *(float2*)(pp + 8*PSTR) = make_float2(c[nj][2], c[nj][3]);
      }
    }
    __syncthreads();

    {
      int q = t >> 3, dq = (t & 7)*4;
      float inv = Sinv[q];
      float4 p0 = *(float4*)(QP + q*PSTR + dq);
      float4 p1 = *(float4*)(QP + 32*PSTR + q*PSTR + dq);
      float4 o = make_float4((p0.x+p1.x)*inv, (p0.y+p1.y)*inv,
                             (p0.z+p1.z)*inv, (p0.w+p1.w)*inv);
      *(float4*)(out + (size_t)(n0 + qt*32 + q)*HIDD + hd*32 + dq) = o;
    }
    __syncthreads();
  }
}

// ================= mean pool =================
__global__ void pool_kernel(const float* __restrict__ fin, float* __restrict__ emb){
  int g = blockIdx.x, d = threadIdx.x;
  float s = 0.f;
  const float* base = fin + (size_t)g*PN*HIDD + d;
  for(int i = 0; i < PN; i++) s += base[(size_t)i*HIDD];
  emb[g*HIDD + d] = s * (1.0f/PN);
}

// ================= launch =================
extern "C" void kernel_launch(void* const* d_in, const int* in_sizes, int n_in,
                              void* d_out, int out_size) {
  const float* x   = (const float*)d_in[0];
  const float* W0  = (const float*)d_in[1];
  const float* b0  = (const float*)d_in[2];
  const float* Wh  = (const float*)d_in[3];
  const float* bh  = (const float*)d_in[4];
  const float* bng = (const float*)d_in[5];
  const float* bnb = (const float*)d_in[6];
  const float* bnm = (const float*)d_in[7];
  const float* bnv = (const float*)d_in[8];
  const float* aiw = (const float*)d_in[9];
  const float* aib = (const float*)d_in[10];
  const float* aow = (const float*)d_in[11];
  const float* aob = (const float*)d_in[12];
  const int*  eidx = (const int*)d_in[13];

  float* out_final = (float*)d_out;
  float* out_emb   = out_final + (size_t)NN*HIDD;

  const int* src = eidx;
  const int* dst = eidx + NE;

  float *p_h, *p_agg, *p_qkv, *p_attno;
  int* p_count;
  cudaGetSymbolAddress((void**)&p_h,     g_h);
  cudaGetSymbolAddress((void**)&p_agg,   g_agg);
  cudaGetSymbolAddress((void**)&p_qkv,   g_qkv);
  cudaGetSymbolAddress((void**)&p_attno, g_attno);
  cudaGetSymbolAddress((void**)&p_count, g_count);

  const int GEMM_SMEM = 2*128*68*4;       // 69632 (both chunk layouts fit)
  const int ATTN_SMEM = ATTN_FLOATS*4;    // 231040
  cudaFuncSetAttribute(gemm_mma_kernel<0,1,64>,  cudaFuncAttributeMaxDynamicSharedMemorySize, GEMM_SMEM);
  cudaFuncSetAttribute(gemm_mma_kernel<0,1,128>, cudaFuncAttributeMaxDynamicSharedMemorySize, GEMM_SMEM);
  cudaFuncSetAttribute(gemm_mma_kernel<1,0,128>, cudaFuncAttributeMaxDynamicSharedMemorySize, GEMM_SMEM);
  cudaFuncSetAttribute(attn_mma_kernel,          cudaFuncAttributeMaxDynamicSharedMemorySize, ATTN_SMEM);

  // CSR build
  cudaMemsetAsync(p_count, 0, NN*sizeof(int));
  count_kernel<<<NE/256, 256>>>(dst);
  scan1_kernel<<<256, 256>>>();
  scan2_kernel<<<1, 256>>>();
  scan3_kernel<<<256, 256>>>();
  fill_kernel<<<NE/256, 256>>>(src, dst);

  // layer 0
  agg64_kernel<<<NN*32/256, 256>>>(x, p_agg);
  gemm_mma_kernel<0,1,64><<<dim3(512,1), 256, GEMM_SMEM>>>(
      p_agg, W0, b0, bng, bnb, bnm, bnv, p_h, 128);

  // layers 1..3
  for(int l = 0; l < 3; l++){
    agg128_kernel<<<NN*32/256, 256>>>(p_h, p_agg);
    gemm_mma_kernel<0,1,128><<<dim3(512,1), 256, GEMM_SMEM>>>(
        p_agg, Wh + (size_t)l*HIDD*HIDD, bh + l*HIDD,
        bng + (l+1)*HIDD, bnb + (l+1)*HIDD, bnm + (l+1)*HIDD, bnv + (l+1)*HIDD,
        p_h, 128);
  }

  // qkv projection
  gemm_mma_kernel<1,0,128><<<dim3(512,3), 256, GEMM_SMEM>>>(
      p_h, aiw, aib, nullptr, nullptr, nullptr, nullptr, p_qkv, 384);

  // attention
  attn_mma_kernel<<<NG*4*2, 256, ATTN_SMEM>>>(p_qkv, p_attno);

  // output projection
  gemm_mma_kernel<1,0,128><<<dim3(512,1), 256, GEMM_SMEM>>>(
      p_attno, aow, aob, nullptr, nullptr, nullptr, nullptr, out_final, 128);

  // mean pool
  pool_kernel<<<NG, HIDD>>>(out_final, out_emb);
}

// round 10
// speedup vs baseline: 3.4133x; 1.0201x over previous
#include <cuda_runtime.h>
#include <cstdint>

#define NN 65536
#define NE (NN*16)
#define NG 128
#define PN 512
#define HIDD 128
#define INDIM 64
#define BN_EPS 1e-5f

__device__ __forceinline__ uint32_t f2tf32(float f){
  uint32_t u; asm("cvt.rna.tf32.f32 %0, %1;" : "=r"(u) : "f"(f)); return u;
}
__device__ __forceinline__ void mma_tf32(float& c0, float& c1, float& c2, float& c3,
                                         uint32_t a0, uint32_t a1, uint32_t a2, uint32_t a3,
                                         uint32_t b0, uint32_t b1){
  asm volatile("mma.sync.aligned.m16n8k8.row.col.f32.tf32.tf32.f32 "
               "{%0,%1,%2,%3}, {%4,%5,%6,%7}, {%8,%9}, {%0,%1,%2,%3};"
               : "+f"(c0), "+f"(c1), "+f"(c2), "+f"(c3)
               : "r"(a0), "r"(a1), "r"(a2), "r"(a3), "r"(b0), "r"(b1));
}
__device__ __forceinline__ uint4 q4(float4 v){
  return make_uint4(f2tf32(v.x), f2tf32(v.y), f2tf32(v.z), f2tf32(v.w));
}

// ================= scratch =================
__device__ int    g_count[NN];
__device__ int    g_rowptr[NN+1];
__device__ int    g_cursor[NN];
__device__ int    g_part[256];
__device__ int    g_poff[256];
__device__ float2 g_edge[NE];     // (src bits, weight)
__device__ float  g_dis[NN];
__device__ float  g_selfn[NN];
__device__ float  g_h[(size_t)NN*HIDD];
__device__ float  g_agg[(size_t)NN*HIDD];
__device__ float  g_qkv[(size_t)NN*3*HIDD];
__device__ float  g_attno[(size_t)NN*HIDD];

// ================= CSR build =================
__global__ void count_kernel(const int* __restrict__ dst){
  int e = blockIdx.x*blockDim.x + threadIdx.x;
  if(e < NE) atomicAdd(&g_count[dst[e]], 1);
}
__global__ void scan1_kernel(){
  __shared__ int wsum[8];
  int b = blockIdx.x, t = threadIdx.x;
  int i = b*256 + t;
  int c = g_count[i];
  float dis = rsqrtf((float)(c + 1));
  g_dis[i] = dis;
  g_selfn[i] = dis*dis;
  int lane = t & 31, w = t >> 5;
  int v = c;
  #pragma unroll
  for(int o=1;o<32;o<<=1){ int u=__shfl_up_sync(0xffffffffu,v,o); if(lane>=o) v+=u; }
  if(lane==31) wsum[w]=v;
  __syncthreads();
  if(w==0){
    int s = (lane<8)? wsum[lane] : 0;
    #pragma unroll
    for(int o=1;o<8;o<<=1){ int u=__shfl_up_sync(0xffffffffu,s,o); if(lane>=o) s+=u; }
    if(lane<8) wsum[lane]=s;
  }
  __syncthreads();
  int excl = v - c + (w ? wsum[w-1] : 0);
  g_rowptr[i] = excl;
  if(t==255) g_part[b] = excl + c;
}
__global__ void scan2_kernel(){
  __shared__ int wsum[8];
  int t = threadIdx.x;
  int v = g_part[t];
  int lane = t & 31, w = t >> 5;
  int s = v;
  #pragma unroll
  for(int o=1;o<32;o<<=1){ int u=__shfl_up_sync(0xffffffffu,s,o); if(lane>=o) s+=u; }
  if(lane==31) wsum[w]=s;
  __syncthreads();
  if(w==0){
    int x = (lane<8)? wsum[lane] : 0;
    #pragma unroll
    for(int o=1;o<8;o<<=1){ int u=__shfl_up_sync(0xffffffffu,x,o); if(lane>=o) x+=u; }
    if(lane<8) wsum[lane]=x;
  }
  __syncthreads();
  g_poff[t] = s - v + (w ? wsum[w-1] : 0);
}
__global__ void scan3_kernel(){
  int b = blockIdx.x, t = threadIdx.x;
  int i = b*256 + t;
  int r = g_rowptr[i] + g_poff[b];
  g_rowptr[i] = r;
  g_cursor[i] = r;
  if(i == 0) g_rowptr[NN] = NE;
}
__global__ void fill_kernel(const int* __restrict__ src, const int* __restrict__ dst){
  int e = blockIdx.x*blockDim.x + threadIdx.x;
  if(e >= NE) return;
  int s = src[e], d = dst[e];
  int pos = atomicAdd(&g_cursor[d], 1);
  g_edge[pos] = make_float2(__int_as_float(s), g_dis[s]*g_dis[d]);
}

// ======== aggregation (warp per node; edge records prefetched + shfl-broadcast) ========
__global__ void agg64_kernel(const float* __restrict__ hin, float* __restrict__ out){
  int gw = (blockIdx.x*blockDim.x + threadIdx.x) >> 5;
  int lane = threadIdx.x & 31;
  if(gw >= NN) return;
  float2 a = *((const float2*)(hin + (size_t)gw*INDIM) + lane);
  float sn = g_selfn[gw];
  a.x *= sn; a.y *= sn;
  int beg = g_rowptr[gw], end = g_rowptr[gw+1];
  for(int b = beg; b < end; b += 32){
    int m = min(32, end - b);
    float2 myed = make_float2(0.f, 0.f);
    if(lane < m) myed = g_edge[b + lane];
    #pragma unroll 2
    for(int i = 0; i < m; i++){
      int   s = __shfl_sync(0xffffffffu, __float_as_int(myed.x), i);
      float w = __shfl_sync(0xffffffffu, myed.y, i);
      float2 v = *((const float2*)(hin + (size_t)s*INDIM) + lane);
      a.x += w*v.x; a.y += w*v.y;
    }
  }
  *((float2*)(out + (size_t)gw*INDIM) + lane) = a;
}
__global__ void agg128_kernel(const float* __restrict__ hin, float* __restrict__ out){
  int gw = (blockIdx.x*blockDim.x + threadIdx.x) >> 5;
  int lane = threadIdx.x & 31;
  if(gw >= NN) return;
  float4 a = *((const float4*)(hin + (size_t)gw*HIDD) + lane);
  float sn = g_selfn[gw];
  a.x *= sn; a.y *= sn; a.z *= sn; a.w *= sn;
  int beg = g_rowptr[gw], end = g_rowptr[gw+1];
  for(int b = beg; b < end; b += 32){
    int m = min(32, end - b);
    float2 myed = make_float2(0.f, 0.f);
    if(lane < m) myed = g_edge[b + lane];
    #pragma unroll 2
    for(int i = 0; i < m; i++){
      int   s = __shfl_sync(0xffffffffu, __float_as_int(myed.x), i);
      float w = __shfl_sync(0xffffffffu, myed.y, i);
      float4 v = *((const float4*)(hin + (size_t)s*HIDD) + lane);
      a.x += w*v.x; a.y += w*v.y; a.z += w*v.z; a.w += w*v.w;
    }
  }
  *((float4*)(out + (size_t)gw*HIDD) + lane) = a;
}

// ================= tf32 mma.sync GEMM (K-chunked staging, 2 CTAs/SM) =================
// POOL=1: also accumulate per-graph column means into emb (rows 512-aligned per graph).
template<int BT, int EPI, int KK, int POOL>
__global__ __launch_bounds__(256, 2)
void gemm_mma_kernel(const float* __restrict__ A, const float* __restrict__ B,
                     const float* __restrict__ bias,
                     const float* __restrict__ bng, const float* __restrict__ bnb,
                     const float* __restrict__ bnm, const float* __restrict__ bnv,
                     float* __restrict__ C, int Ndt, float* __restrict__ emb)
{
  constexpr int CK  = 64;
  constexpr int NCH = KK / CK;
  constexpr int SA  = CK + 4;     // 68
  constexpr int SBN = 132;
  extern __shared__ uint32_t sm[];
  uint32_t* As = sm;              // [128][68]
  uint32_t* Bs = sm + 128*SA;     // BT1: [128][68]; BT0: [64][132]
  const int tid = threadIdx.x;
  const int lane = tid & 31, wid = tid >> 5;
  const int row0 = blockIdx.x * 128;
  const int col0 = blockIdx.y * 128;

  const int m0 = (wid >> 1) * 32;
  const int n0 = (wid & 1) * 64;
  const int g  = lane >> 2;
  const int t4 = lane & 3;

  float acc[2][8][4];
  #pragma unroll
  for(int i=0;i<2;i++)
    #pragma unroll
    for(int j=0;j<8;j++)
      #pragma unroll
      for(int q=0;q<4;q++) acc[i][j][q]=0.f;

  #pragma unroll 1
  for(int ch = 0; ch < NCH; ch++){
    const int kbase = ch*CK;
    for(int idx = tid; idx < 128*16; idx += 256){
      int r = idx >> 4, q = idx & 15;
      float4 v = *(const float4*)(A + (size_t)(row0 + r)*KK + kbase + q*4);
      *(uint4*)(As + r*SA + q*4) = q4(v);
    }
    if(BT){
      for(int idx = tid; idx < 128*16; idx += 256){
        int r = idx >> 4, q = idx & 15;
        float4 v = *(const float4*)(B + (size_t)(col0 + r)*KK + kbase + q*4);
        *(uint4*)(Bs + r*SA + q*4) = q4(v);
      }
    } else {
      for(int idx = tid; idx < CK*32; idx += 256){
        int k = idx >> 5, n4 = idx & 31;
        float4 v = *(const float4*)(B + (size_t)(kbase + k)*Ndt + col0 + n4*4);
        *(uint4*)(Bs + k*SBN + n4*4) = q4(v);
      }
    }
    __syncthreads();

    const uint32_t* Aw0 = As + (m0 + g)*SA + t4;
    const uint32_t* Aw1 = As + (m0 + 16 + g)*SA + t4;
    const uint32_t* Bw1 = Bs + (n0 + g)*SA + t4;
    const uint32_t* Bw0 = Bs + t4*SBN + n0 + g;

    #pragma unroll 1
    for(int ks = 0; ks < CK/8; ks++){
      const int k0 = ks*8;
      uint32_t af[2][4];
      af[0][0] = Aw0[k0];       af[0][1] = Aw0[8*SA + k0];
      af[0][2] = Aw0[k0 + 4];   af[0][3] = Aw0[8*SA + k0 + 4];
      af[1][0] = Aw1[k0];       af[1][1] = Aw1[8*SA + k0];
      af[1][2] = Aw1[k0 + 4];   af[1][3] = Aw1[8*SA + k0 + 4];
      #pragma unroll
      for(int nj = 0; nj < 8; nj++){
        uint32_t b0, b1;
        if(BT){
          b0 = Bw1[nj*8*SA + k0];
          b1 = Bw1[nj*8*SA + k0 + 4];
        } else {
          b0 = Bw0[k0*SBN + nj*8];
          b1 = Bw0[(k0+4)*SBN + nj*8];
        }
        mma_tf32(acc[0][nj][0], acc[0][nj][1], acc[0][nj][2], acc[0][nj][3],
                 af[0][0], af[0][1], af[0][2], af[0][3], b0, b1);
        mma_tf32(acc[1][nj][0], acc[1][nj][1], acc[1][nj][2], acc[1][nj][3],
                 af[1][0], af[1][1], af[1][2], af[1][3], b0, b1);
      }
    }
    if(ch + 1 < NCH) __syncthreads();
  }

  float cs[8][2];
  if(POOL){
    #pragma unroll
    for(int nj=0;nj<8;nj++){ cs[nj][0]=0.f; cs[nj][1]=0.f; }
  }

  #pragma unroll
  for(int mi = 0; mi < 2; mi++){
    #pragma unroll
    for(int nj = 0; nj < 8; nj++){
      int c = col0 + n0 + nj*8 + t4*2;
      float s0, s1;
      if(EPI){
        s0 = bng[c  ]*rsqrtf(bnv[c  ] + BN_EPS);
        s1 = bng[c+1]*rsqrtf(bnv[c+1] + BN_EPS);
      }
      #pragma unroll
      for(int h = 0; h < 2; h++){
        int r = row0 + m0 + mi*16 + g + h*8;
        float v0 = acc[mi][nj][h*2+0] + bias[c];
        float v1 = acc[mi][nj][h*2+1] + bias[c+1];
        if(EPI){
          v0 = fmaxf((v0 - bnm[c  ])*s0 + bnb[c  ], 0.f);
          v1 = fmaxf((v1 - bnm[c+1])*s1 + bnb[c+1], 0.f);
        }
        if(POOL){ cs[nj][0] += v0; cs[nj][1] += v1; }
        *(float2*)(C + (size_t)r*Ndt + c) = make_float2(v0, v1);
      }
    }
  }

  if(POOL){
    int graph = row0 >> 9;       // PN=512 rows per graph; tile fully inside one graph
    #pragma unroll
    for(int nj = 0; nj < 8; nj++){
      float s0 = cs[nj][0], s1 = cs[nj][1];
      #pragma unroll
      for(int o = 4; o <= 16; o <<= 1){
        s0 += __shfl_xor_sync(0xffffffffu, s0, o);
        s1 += __shfl_xor_sync(0xffffffffu, s1, o);
      }
      if(g == 0){
        int c = col0 + n0 + nj*8 + t4*2;
        atomicAdd(&emb[graph*HIDD + c],   s0*(1.0f/PN));
        atomicAdd(&emb[graph*HIDD + c+1], s1*(1.0f/PN));
      }
    }
  }
}

// ================= attention via tf32 mma: CTA per (graph, head, half) ===========
// smem floats: Ks[512][36] | Vs[512][40] | S[32][516] | Q[32][36] | Sinv[32]
#define KSTR 36
#define VSTR 40
#define SSTR 516
#define QSTR 36
#define KS_OFF 0
#define VS_OFF (512*KSTR)                 // 18432
#define S_OFF  (VS_OFF + 512*VSTR)        // 38912
#define Q_OFF  (S_OFF + 32*SSTR)          // 55424
#define SINV_OFF (Q_OFF + 32*QSTR)        // 56576
#define ATTN_FLOATS (SINV_OFF + 32)       // 56608

__global__ __launch_bounds__(256)
void attn_mma_kernel(const float* __restrict__ qkv, float* __restrict__ out){
  extern __shared__ float smf[];
  float* S    = smf + S_OFF;
  float* Sinv = smf + SINV_OFF;
  uint32_t* Ku = (uint32_t*)(smf + KS_OFF);
  uint32_t* Vu = (uint32_t*)(smf + VS_OFF);
  uint32_t* Su = (uint32_t*)S;
  uint32_t* Qu = (uint32_t*)(smf + Q_OFF);

  int g    = blockIdx.x >> 3;
  int hd   = (blockIdx.x >> 1) & 3;
  int half = blockIdx.x & 1;
  int n0 = g*PN;
  int t = threadIdx.x;
  int lane = t & 31, warp = t >> 5;
  int gq = lane >> 2, t4 = lane & 3;
  const float scale = 0.17677669529663687f;

  for(int idx = t; idx < PN*8; idx += 256){
    int r = idx >> 3, d4 = (idx & 7)*4;
    const float* row = qkv + (size_t)(n0 + r)*384 + hd*32;
    *(uint4*)(Ku + r*KSTR + d4) = q4(*(const float4*)(row + 128 + d4));
    *(uint4*)(Vu + r*VSTR + d4) = q4(*(const float4*)(row + 256 + d4));
  }
  __syncthreads();

  for(int qi8 = 0; qi8 < 8; qi8++){
    int qt = half*8 + qi8;
    // stage Q tile (scale folded)
    for(int idx = t; idx < 32*8; idx += 256){
      int r = idx >> 3, d4 = (idx & 7)*4;
      float4 qv = *(const float4*)(qkv + (size_t)(n0 + qt*32 + r)*384 + hd*32 + d4);
      qv.x *= scale; qv.y *= scale; qv.z *= scale; qv.w *= scale;
      *(uint4*)(Qu + r*QSTR + d4) = q4(qv);
    }
    __syncthreads();

    // Phase A: S = Qs K^T  (warp covers all 32 q-rows x 64 keys)
    {
      float c[2][8][4];
      #pragma unroll
      for(int i=0;i<2;i++)
        #pragma unroll
        for(int j=0;j<8;j++)
          #pragma unroll
          for(int q=0;q<4;q++) c[i][j][q]=0.f;

      #pragma unroll 1
      for(int ks = 0; ks < 4; ks++){
        int k0 = ks*8;
        uint32_t a[2][4];
        #pragma unroll
        for(int mi=0;mi<2;mi++){
          const uint32_t* qb = Qu + (mi*16+gq)*QSTR + k0 + t4;
          a[mi][0]=qb[0]; a[mi][1]=qb[8*QSTR]; a[mi][2]=qb[4]; a[mi][3]=qb[8*QSTR+4];
        }
        #pragma unroll
        for(int nj=0;nj<8;nj++){
          const uint32_t* kb = Ku + (warp*64+nj*8+gq)*KSTR + k0 + t4;
          uint32_t b0 = kb[0], b1 = kb[4];
          mma_tf32(c[0][nj][0],c[0][nj][1],c[0][nj][2],c[0][nj][3],
                   a[0][0],a[0][1],a[0][2],a[0][3], b0,b1);
          mma_tf32(c[1][nj][0],c[1][nj][1],c[1][nj][2],c[1][nj][3],
                   a[1][0],a[1][1],a[1][2],a[1][3], b0,b1);
        }
      }
      #pragma unroll
      for(int mi=0;mi<2;mi++)
        #pragma unroll
        for(int nj=0;nj<8;nj++){
          float* sp = S + (mi*16+gq)*SSTR + warp*64 + nj*8 + t4*2;
          *(float2*)(sp)          = make_float2(c[mi][nj][0], c[mi][nj][1]);
          *(float2*)(sp + 8*SSTR) = make_float2(c[mi][nj][2], c[mi][nj][3]);
        }
    }
    __syncthreads();

    // Phase B: single-pass exp + sum (float4); normalization deferred
    for(int rr = 0; rr < 4; rr++){
      int r = warp*4 + rr;
      float sum = 0.f;
      float* Srow = S + r*SSTR;
      #pragma unroll
      for(int jj = 0; jj < 4; jj++){
        int j4 = (jj*32 + lane)*4;
        float4 v = *(float4*)(Srow + j4);
        v.x = __expf(v.x); v.y = __expf(v.y); v.z = __expf(v.z); v.w = __expf(v.w);
        sum += v.x + v.y + v.z + v.w;
        uint4 tv = q4(v);
        *(uint4*)((uint32_t*)Srow + j4) = tv;
      }
      #pragma unroll
      for(int o=16;o;o>>=1) sum += __shfl_xor_sync(0xffffffffu, sum, o);
      if(lane == 0) Sinv[r] = 1.f/sum;
    }
    __syncthreads();

    // Phase C: O = (E V) * Sinv  — warp = (mi = warp&1) x (ni = warp>>1), full k sweep
    {
      int mi = warp & 1, ni = warp >> 1;
      float c0=0.f,c1=0.f,c2=0.f,c3=0.f;
      const uint32_t* pbase = Su + (mi*16+gq)*SSTR + t4;
      const uint32_t* vbase = Vu + t4*VSTR + ni*8 + gq;
      #pragma unroll 4
      for(int ks = 0; ks < 64; ks++){
        int k0 = ks*8;
        uint32_t a0 = pbase[k0], a1 = pbase[8*SSTR + k0];
        uint32_t a2 = pbase[k0+4], a3 = pbase[8*SSTR + k0+4];
        uint32_t b0 = vbase[k0*VSTR], b1 = vbase[(k0+4)*VSTR];
        mma_tf32(c0,c1,c2,c3, a0,a1,a2,a3, b0,b1);
      }
      int r0 = mi*16 + gq;
      float inv0 = Sinv[r0], inv1 = Sinv[r0+8];
      float* ob = out + (size_t)(n0 + qt*32)*HIDD + hd*32 + ni*8 + t4*2;
      *(float2*)(ob + (size_t)r0*HIDD)     = make_float2(c0*inv0, c1*inv0);
      *(float2*)(ob + (size_t)(r0+8)*HIDD) = make_float2(c2*inv1, c3*inv1);
    }
    __syncthreads();
  }
}

// ================= launch =================
extern "C" void kernel_launch(void* const* d_in, const int* in_sizes, int n_in,
                              void* d_out, int out_size) {
  const float* x   = (const float*)d_in[0];
  const float* W0  = (const float*)d_in[1];
  const float* b0  = (const float*)d_in[2];
  const float* Wh  = (const float*)d_in[3];
  const float* bh  = (const float*)d_in[4];
  const float* bng = (const float*)d_in[5];
  const float* bnb = (const float*)d_in[6];
  const float* bnm = (const float*)d_in[7];
  const float* bnv = (const float*)d_in[8];
  const float* aiw = (const float*)d_in[9];
  const float* aib = (const float*)d_in[10];
  const float* aow = (const float*)d_in[11];
  const float* aob = (const float*)d_in[12];
  const int*  eidx = (const int*)d_in[13];

  float* out_final = (float*)d_out;
  float* out_emb   = out_final + (size_t)NN*HIDD;

  const int* src = eidx;
  const int* dst = eidx + NE;

  float *p_h, *p_agg, *p_qkv, *p_attno;
  int* p_count;
  cudaGetSymbolAddress((void**)&p_h,     g_h);
  cudaGetSymbolAddress((void**)&p_agg,   g_agg);
  cudaGetSymbolAddress((void**)&p_qkv,   g_qkv);
  cudaGetSymbolAddress((void**)&p_attno, g_attno);
  cudaGetSymbolAddress((void**)&p_count, g_count);

  const int GEMM_SMEM = 2*128*68*4;       // 69632
  const int ATTN_SMEM = ATTN_FLOATS*4;    // 226432
  cudaFuncSetAttribute(gemm_mma_kernel<0,1,64,0>,  cudaFuncAttributeMaxDynamicSharedMemorySize, GEMM_SMEM);
  cudaFuncSetAttribute(gemm_mma_kernel<0,1,128,0>, cudaFuncAttributeMaxDynamicSharedMemorySize, GEMM_SMEM);
  cudaFuncSetAttribute(gemm_mma_kernel<1,0,128,0>, cudaFuncAttributeMaxDynamicSharedMemorySize, GEMM_SMEM);
  cudaFuncSetAttribute(gemm_mma_kernel<1,0,128,1>, cudaFuncAttributeMaxDynamicSharedMemorySize, GEMM_SMEM);
  cudaFuncSetAttribute(attn_mma_kernel,            cudaFuncAttributeMaxDynamicSharedMemorySize, ATTN_SMEM);

  // CSR build
  cudaMemsetAsync(p_count, 0, NN*sizeof(int));
  count_kernel<<<NE/256, 256>>>(dst);
  scan1_kernel<<<256, 256>>>();
  scan2_kernel<<<1, 256>>>();
  scan3_kernel<<<256, 256>>>();
  fill_kernel<<<NE/256, 256>>>(src, dst);

  // layer 0
  agg64_kernel<<<NN*32/256, 256>>>(x, p_agg);
  gemm_mma_kernel<0,1,64,0><<<dim3(512,1), 256, GEMM_SMEM>>>(
      p_agg, W0, b0, bng, bnb, bnm, bnv, p_h, 128, nullptr);

  // layers 1..3
  for(int l = 0; l < 3; l++){
    agg128_kernel<<<NN*32/256, 256>>>(p_h, p_agg);
    gemm_mma_kernel<0,1,128,0><<<dim3(512,1), 256, GEMM_SMEM>>>(
        p_agg, Wh + (size_t)l*HIDD*HIDD, bh + l*HIDD,
        bng + (l+1)*HIDD, bnb + (l+1)*HIDD, bnm + (l+1)*HIDD, bnv + (l+1)*HIDD,
        p_h, 128, nullptr);
  }

  // qkv projection
  gemm_mma_kernel<1,0,128,0><<<dim3(512,3), 256, GEMM_SMEM>>>(
      p_h, aiw, aib, nullptr, nullptr, nullptr, nullptr, p_qkv, 384, nullptr);

  // attention
  attn_mma_kernel<<<NG*4*2, 256, ATTN_SMEM>>>(p_qkv, p_attno);

  // output projection + fused mean pool
  cudaMemsetAsync(out_emb, 0, NG*HIDD*sizeof(float));
  gemm_mma_kernel<1,0,128,1><<<dim3(512,1), 256, GEMM_SMEM>>>(
      p_attno, aow, aob, nullptr, nullptr, nullptr, nullptr, out_final, 128, out_emb);
}

// round 11
// speedup vs baseline: 3.4135x; 1.0000x over previous
#include <cuda_runtime.h>
#include <cstdint>

#define NN 65536
#define NE (NN*16)
#define NG 128
#define PN 512
#define HIDD 128
#define INDIM 64
#define BN_EPS 1e-5f

__device__ __forceinline__ uint32_t f2tf32(float f){
  uint32_t u; asm("cvt.rna.tf32.f32 %0, %1;" : "=r"(u) : "f"(f)); return u;
}
__device__ __forceinline__ void mma_tf32(float& c0, float& c1, float& c2, float& c3,
                                         uint32_t a0, uint32_t a1, uint32_t a2, uint32_t a3,
                                         uint32_t b0, uint32_t b1){
  asm volatile("mma.sync.aligned.m16n8k8.row.col.f32.tf32.tf32.f32 "
               "{%0,%1,%2,%3}, {%4,%5,%6,%7}, {%8,%9}, {%0,%1,%2,%3};"
               : "+f"(c0), "+f"(c1), "+f"(c2), "+f"(c3)
               : "r"(a0), "r"(a1), "r"(a2), "r"(a3), "r"(b0), "r"(b1));
}
__device__ __forceinline__ uint4 q4(float4 v){
  return make_uint4(f2tf32(v.x), f2tf32(v.y), f2tf32(v.z), f2tf32(v.w));
}

// ================= scratch =================
__device__ int    g_count[NN];
__device__ int    g_rowptr[NN+1];
__device__ int    g_cursor[NN];
__device__ int    g_part[256];
__device__ int    g_poff[256];
__device__ float2 g_edge[NE];     // (src bits, weight)
__device__ float  g_dis[NN];
__device__ float  g_selfn[NN];
__device__ float  g_h[(size_t)NN*HIDD];
__device__ float  g_agg[(size_t)NN*HIDD];
__device__ float  g_qkv[(size_t)NN*3*HIDD];
__device__ float  g_attno[(size_t)NN*HIDD];
__device__ uint32_t g_wr[122880];   // pre-rounded weights: W0|Wh|aiw|aow

// ================= weight pre-round (tf32) =================
__global__ void roundw_kernel(const float* __restrict__ W0, const float* __restrict__ Wh,
                              const float* __restrict__ aiw, const float* __restrict__ aow){
  int i = (blockIdx.x*256 + threadIdx.x)*4;
  float4 v;
  if(i < 8192)        v = *(const float4*)(W0 + i);
  else if(i < 57344)  v = *(const float4*)(Wh + (i - 8192));
  else if(i < 106496) v = *(const float4*)(aiw + (i - 57344));
  else                v = *(const float4*)(aow + (i - 106496));
  *(uint4*)(g_wr + i) = q4(v);
}

// ================= CSR build =================
__global__ void count_kernel(const int* __restrict__ dst){
  int e = blockIdx.x*blockDim.x + threadIdx.x;
  if(e < NE) atomicAdd(&g_count[dst[e]], 1);
}
__global__ void scan1_kernel(){
  __shared__ int wsum[8];
  int b = blockIdx.x, t = threadIdx.x;
  int i = b*256 + t;
  int c = g_count[i];
  float dis = rsqrtf((float)(c + 1));
  g_dis[i] = dis;
  g_selfn[i] = dis*dis;
  int lane = t & 31, w = t >> 5;
  int v = c;
  #pragma unroll
  for(int o=1;o<32;o<<=1){ int u=__shfl_up_sync(0xffffffffu,v,o); if(lane>=o) v+=u; }
  if(lane==31) wsum[w]=v;
  __syncthreads();
  if(w==0){
    int s = (lane<8)? wsum[lane] : 0;
    #pragma unroll
    for(int o=1;o<8;o<<=1){ int u=__shfl_up_sync(0xffffffffu,s,o); if(lane>=o) s+=u; }
    if(lane<8) wsum[lane]=s;
  }
  __syncthreads();
  int excl = v - c + (w ? wsum[w-1] : 0);
  g_rowptr[i] = excl;
  if(t==255) g_part[b] = excl + c;
}
__global__ void scan2_kernel(){
  __shared__ int wsum[8];
  int t = threadIdx.x;
  int v = g_part[t];
  int lane = t & 31, w = t >> 5;
  int s = v;
  #pragma unroll
  for(int o=1;o<32;o<<=1){ int u=__shfl_up_sync(0xffffffffu,s,o); if(lane>=o) s+=u; }
  if(lane==31) wsum[w]=s;
  __syncthreads();
  if(w==0){
    int x = (lane<8)? wsum[lane] : 0;
    #pragma unroll
    for(int o=1;o<8;o<<=1){ int u=__shfl_up_sync(0xffffffffu,x,o); if(lane>=o) x+=u; }
    if(lane<8) wsum[lane]=x;
  }
  __syncthreads();
  g_poff[t] = s - v + (w ? wsum[w-1] : 0);
}
__global__ void scan3_kernel(){
  int b = blockIdx.x, t = threadIdx.x;
  int i = b*256 + t;
  int r = g_rowptr[i] + g_poff[b];
  g_rowptr[i] = r;
  g_cursor[i] = r;
  if(i == 0) g_rowptr[NN] = NE;
}
__global__ void fill_kernel(const int* __restrict__ src, const int* __restrict__ dst){
  int e = blockIdx.x*blockDim.x + threadIdx.x;
  if(e >= NE) return;
  int s = src[e], d = dst[e];
  int pos = atomicAdd(&g_cursor[d], 1);
  g_edge[pos] = make_float2(__int_as_float(s), g_dis[s]*g_dis[d]);
}

// ======== aggregation (warp/node; edge prefetch + shfl bcast; tf32-rounded output) ========
__global__ void agg64_kernel(const float* __restrict__ hin, float* __restrict__ out){
  int gw = (blockIdx.x*blockDim.x + threadIdx.x) >> 5;
  int lane = threadIdx.x & 31;
  if(gw >= NN) return;
  float2 a = *((const float2*)(hin + (size_t)gw*INDIM) + lane);
  float sn = g_selfn[gw];
  a.x *= sn; a.y *= sn;
  int beg = g_rowptr[gw], end = g_rowptr[gw+1];
  for(int b = beg; b < end; b += 32){
    int m = min(32, end - b);
    float2 myed = make_float2(0.f, 0.f);
    if(lane < m) myed = g_edge[b + lane];
    #pragma unroll 2
    for(int i = 0; i < m; i++){
      int   s = __shfl_sync(0xffffffffu, __float_as_int(myed.x), i);
      float w = __shfl_sync(0xffffffffu, myed.y, i);
      float2 v = *((const float2*)(hin + (size_t)s*INDIM) + lane);
      a.x += w*v.x; a.y += w*v.y;
    }
  }
  *((uint2*)(out + (size_t)gw*INDIM) + lane) = make_uint2(f2tf32(a.x), f2tf32(a.y));
}
__global__ void agg128_kernel(const float* __restrict__ hin, float* __restrict__ out){
  int gw = (blockIdx.x*blockDim.x + threadIdx.x) >> 5;
  int lane = threadIdx.x & 31;
  if(gw >= NN) return;
  float4 a = *((const float4*)(hin + (size_t)gw*HIDD) + lane);
  float sn = g_selfn[gw];
  a.x *= sn; a.y *= sn; a.z *= sn; a.w *= sn;
  int beg = g_rowptr[gw], end = g_rowptr[gw+1];
  for(int b = beg; b < end; b += 32){
    int m = min(32, end - b);
    float2 myed = make_float2(0.f, 0.f);
    if(lane < m) myed = g_edge[b + lane];
    #pragma unroll 2
    for(int i = 0; i < m; i++){
      int   s = __shfl_sync(0xffffffffu, __float_as_int(myed.x), i);
      float w = __shfl_sync(0xffffffffu, myed.y, i);
      float4 v = *((const float4*)(hin + (size_t)s*HIDD) + lane);
      a.x += w*v.x; a.y += w*v.y; a.z += w*v.z; a.w += w*v.w;
    }
  }
  *((uint4*)(out + (size_t)gw*HIDD) + lane) = q4(a);
}

// ================= tf32 mma.sync GEMM (pre-rounded operands; pure-copy staging) =======
// A and B point to tf32-bit data. RND=1: round outputs (h / qkv). POOL=1: fused mean pool.
template<int BT, int EPI, int KK, int POOL, int RND>
__global__ __launch_bounds__(256, 2)
void gemm_mma_kernel(const float* __restrict__ A, const uint32_t* __restrict__ B,
                     const float* __restrict__ bias,
                     const float* __restrict__ bng, const float* __restrict__ bnb,
                     const float* __restrict__ bnm, const float* __restrict__ bnv,
                     float* __restrict__ C, int Ndt, float* __restrict__ emb)
{
  constexpr int CK  = 64;
  constexpr int NCH = KK / CK;
  constexpr int SA  = CK + 4;     // 68
  constexpr int SBN = 132;
  extern __shared__ uint32_t sm[];
  uint32_t* As = sm;              // [128][68]
  uint32_t* Bs = sm + 128*SA;     // BT1: [128][68]; BT0: [64][132]
  const int tid = threadIdx.x;
  const int lane = tid & 31, wid = tid >> 5;
  const int row0 = blockIdx.x * 128;
  const int col0 = blockIdx.y * 128;

  const int m0 = (wid >> 1) * 32;
  const int n0 = (wid & 1) * 64;
  const int g  = lane >> 2;
  const int t4 = lane & 3;

  float acc[2][8][4];
  #pragma unroll
  for(int i=0;i<2;i++)
    #pragma unroll
    for(int j=0;j<8;j++)
      #pragma unroll
      for(int q=0;q<4;q++) acc[i][j][q]=0.f;

  #pragma unroll 1
  for(int ch = 0; ch < NCH; ch++){
    const int kbase = ch*CK;
    for(int idx = tid; idx < 128*16; idx += 256){
      int r = idx >> 4, q = idx & 15;
      *(uint4*)(As + r*SA + q*4) =
        *(const uint4*)((const uint32_t*)A + (size_t)(row0 + r)*KK + kbase + q*4);
    }
    if(BT){
      for(int idx = tid; idx < 128*16; idx += 256){
        int r = idx >> 4, q = idx & 15;
        *(uint4*)(Bs + r*SA + q*4) =
          *(const uint4*)(B + (size_t)(col0 + r)*KK + kbase + q*4);
      }
    } else {
      for(int idx = tid; idx < CK*32; idx += 256){
        int k = idx >> 5, n4 = idx & 31;
        *(uint4*)(Bs + k*SBN + n4*4) =
          *(const uint4*)(B + (size_t)(kbase + k)*Ndt + col0 + n4*4);
      }
    }
    __syncthreads();

    const uint32_t* Aw0 = As + (m0 + g)*SA + t4;
    const uint32_t* Aw1 = As + (m0 + 16 + g)*SA + t4;
    const uint32_t* Bw1 = Bs + (n0 + g)*SA + t4;
    const uint32_t* Bw0 = Bs + t4*SBN + n0 + g;

    #pragma unroll 1
    for(int ks = 0; ks < CK/8; ks++){
      const int k0 = ks*8;
      uint32_t af[2][4];
      af[0][0] = Aw0[k0];       af[0][1] = Aw0[8*SA + k0];
      af[0][2] = Aw0[k0 + 4];   af[0][3] = Aw0[8*SA + k0 + 4];
      af[1][0] = Aw1[k0];       af[1][1] = Aw1[8*SA + k0];
      af[1][2] = Aw1[k0 + 4];   af[1][3] = Aw1[8*SA + k0 + 4];
      #pragma unroll
      for(int nj = 0; nj < 8; nj++){
        uint32_t b0, b1;
        if(BT){
          b0 = Bw1[nj*8*SA + k0];
          b1 = Bw1[nj*8*SA + k0 + 4];
        } else {
          b0 = Bw0[k0*SBN + nj*8];
          b1 = Bw0[(k0+4)*SBN + nj*8];
        }
        mma_tf32(acc[0][nj][0], acc[0][nj][1], acc[0][nj][2], acc[0][nj][3],
                 af[0][0], af[0][1], af[0][2], af[0][3], b0, b1);
        mma_tf32(acc[1][nj][0], acc[1][nj][1], acc[1][nj][2], acc[1][nj][3],
                 af[1][0], af[1][1], af[1][2], af[1][3], b0, b1);
      }
    }
    if(ch + 1 < NCH) __syncthreads();
  }

  float cs[8][2];
  if(POOL){
    #pragma unroll
    for(int nj=0;nj<8;nj++){ cs[nj][0]=0.f; cs[nj][1]=0.f; }
  }

  #pragma unroll
  for(int mi = 0; mi < 2; mi++){
    #pragma unroll
    for(int nj = 0; nj < 8; nj++){
      int c = col0 + n0 + nj*8 + t4*2;
      float s0, s1;
      if(EPI){
        s0 = bng[c  ]*rsqrtf(bnv[c  ] + BN_EPS);
        s1 = bng[c+1]*rsqrtf(bnv[c+1] + BN_EPS);
      }
      #pragma unroll
      for(int h = 0; h < 2; h++){
        int r = row0 + m0 + mi*16 + g + h*8;
        float v0 = acc[mi][nj][h*2+0] + bias[c];
        float v1 = acc[mi][nj][h*2+1] + bias[c+1];
        if(EPI){
          v0 = fmaxf((v0 - bnm[c  ])*s0 + bnb[c  ], 0.f);
          v1 = fmaxf((v1 - bnm[c+1])*s1 + bnb[c+1], 0.f);
        }
        if(POOL){ cs[nj][0] += v0; cs[nj][1] += v1; }
        if(RND){
          *(uint2*)(C + (size_t)r*Ndt + c) = make_uint2(f2tf32(v0), f2tf32(v1));
        } else {
          *(float2*)(C + (size_t)r*Ndt + c) = make_float2(v0, v1);
        }
      }
    }
  }

  if(POOL){
    int graph = row0 >> 9;
    #pragma unroll
    for(int nj = 0; nj < 8; nj++){
      float s0 = cs[nj][0], s1 = cs[nj][1];
      #pragma unroll
      for(int o = 4; o <= 16; o <<= 1){
        s0 += __shfl_xor_sync(0xffffffffu, s0, o);
        s1 += __shfl_xor_sync(0xffffffffu, s1, o);
      }
      if(g == 0){
        int c = col0 + n0 + nj*8 + t4*2;
        atomicAdd(&emb[graph*HIDD + c],   s0*(1.0f/PN));
        atomicAdd(&emb[graph*HIDD + c+1], s1*(1.0f/PN));
      }
    }
  }
}

// ================= attention via tf32 mma: CTA per (graph, head, half) ===========
// qkv is pre-rounded tf32 bits -> staging is pure copy; 1/sqrt(32) folded into exp.
#define KSTR 36
#define VSTR 40
#define SSTR 516
#define QSTR 36
#define KS_OFF 0
#define VS_OFF (512*KSTR)
#define S_OFF  (VS_OFF + 512*VSTR)
#define Q_OFF  (S_OFF + 32*SSTR)
#define SINV_OFF (Q_OFF + 32*QSTR)
#define ATTN_FLOATS (SINV_OFF + 32)

__global__ __launch_bounds__(256)
void attn_mma_kernel(const float* __restrict__ qkv, float* __restrict__ out){
  extern __shared__ float smf[];
  float* S    = smf + S_OFF;
  float* Sinv = smf + SINV_OFF;
  uint32_t* Ku = (uint32_t*)(smf + KS_OFF);
  uint32_t* Vu = (uint32_t*)(smf + VS_OFF);
  uint32_t* Su = (uint32_t*)S;
  uint32_t* Qu = (uint32_t*)(smf + Q_OFF);

  int g    = blockIdx.x >> 3;
  int hd   = (blockIdx.x >> 1) & 3;
  int half = blockIdx.x & 1;
  int n0 = g*PN;
  int t = threadIdx.x;
  int lane = t & 31, warp = t >> 5;
  int gq = lane >> 2, t4 = lane & 3;
  const float scale = 0.17677669529663687f;   // 1/sqrt(32), folded into exp

  for(int idx = t; idx < PN*8; idx += 256){
    int r = idx >> 3, d4 = (idx & 7)*4;
    const uint32_t* row = (const uint32_t*)qkv + (size_t)(n0 + r)*384 + hd*32;
    *(uint4*)(Ku + r*KSTR + d4) = *(const uint4*)(row + 128 + d4);
    *(uint4*)(Vu + r*VSTR + d4) = *(const uint4*)(row + 256 + d4);
  }
  __syncthreads();

  for(int qi8 = 0; qi8 < 8; qi8++){
    int qt = half*8 + qi8;
    for(int idx = t; idx < 32*8; idx += 256){
      int r = idx >> 3, d4 = (idx & 7)*4;
      *(uint4*)(Qu + r*QSTR + d4) =
        *(const uint4*)((const uint32_t*)qkv + (size_t)(n0 + qt*32 + r)*384 + hd*32 + d4);
    }
    __syncthreads();

    // Phase A: S = Q K^T (unscaled)
    {
      float c[2][8][4];
      #pragma unroll
      for(int i=0;i<2;i++)
        #pragma unroll
        for(int j=0;j<8;j++)
          #pragma unroll
          for(int q=0;q<4;q++) c[i][j][q]=0.f;

      #pragma unroll 1
      for(int ks = 0; ks < 4; ks++){
        int k0 = ks*8;
        uint32_t a[2][4];
        #pragma unroll
        for(int mi=0;mi<2;mi++){
          const uint32_t* qb = Qu + (mi*16+gq)*QSTR + k0 + t4;
          a[mi][0]=qb[0]; a[mi][1]=qb[8*QSTR]; a[mi][2]=qb[4]; a[mi][3]=qb[8*QSTR+4];
        }
        #pragma unroll
        for(int nj=0;nj<8;nj++){
          const uint32_t* kb = Ku + (warp*64+nj*8+gq)*KSTR + k0 + t4;
          uint32_t b0 = kb[0], b1 = kb[4];
          mma_tf32(c[0][nj][0],c[0][nj][1],c[0][nj][2],c[0][nj][3],
                   a[0][0],a[0][1],a[0][2],a[0][3], b0,b1);
          mma_tf32(c[1][nj][0],c[1][nj][1],c[1][nj][2],c[1][nj][3],
                   a[1][0],a[1][1],a[1][2],a[1][3], b0,b1);
        }
      }
      #pragma unroll
      for(int mi=0;mi<2;mi++)
        #pragma unroll
        for(int nj=0;nj<8;nj++){
          float* sp = S + (mi*16+gq)*SSTR + warp*64 + nj*8 + t4*2;
          *(float2*)(sp)          = make_float2(c[mi][nj][0], c[mi][nj][1]);
          *(float2*)(sp + 8*SSTR) = make_float2(c[mi][nj][2], c[mi][nj][3]);
        }
    }
    __syncthreads();

    // Phase B: exp(s*scale) + sum (float4); normalization deferred
    for(int rr = 0; rr < 4; rr++){
      int r = warp*4 + rr;
      float sum = 0.f;
      float* Srow = S + r*SSTR;
      #pragma unroll
      for(int jj = 0; jj < 4; jj++){
        int j4 = (jj*32 + lane)*4;
        float4 v = *(float4*)(Srow + j4);
        v.x = __expf(v.x*scale); v.y = __expf(v.y*scale);
        v.z = __expf(v.z*scale); v.w = __expf(v.w*scale);
        sum += v.x + v.y + v.z + v.w;
        *(uint4*)((uint32_t*)Srow + j4) = q4(v);
      }
      #pragma unroll
      for(int o=16;o;o>>=1) sum += __shfl_xor_sync(0xffffffffu, sum, o);
      if(lane == 0) Sinv[r] = 1.f/sum;
    }
    __syncthreads();

    // Phase C: O = (E V) * Sinv; output rounded (feeds final GEMM)
    {
      int mi = warp & 1, ni = warp >> 1;
      float c0=0.f,c1=0.f,c2=0.f,c3=0.f;
      const uint32_t* pbase = Su + (mi*16+gq)*SSTR + t4;
      const uint32_t* vbase = Vu + t4*VSTR + ni*8 + gq;
      #pragma unroll 4
      for(int ks = 0; ks < 64; ks++){
        int k0 = ks*8;
        uint32_t a0 = pbase[k0], a1 = pbase[8*SSTR + k0];
        uint32_t a2 = pbase[k0+4], a3 = pbase[8*SSTR + k0+4];
        uint32_t b0 = vbase[k0*VSTR], b1 = vbase[(k0+4)*VSTR];
        mma_tf32(c0,c1,c2,c3, a0,a1,a2,a3, b0,b1);
      }
      int r0 = mi*16 + gq;
      float inv0 = Sinv[r0], inv1 = Sinv[r0+8];
      float* ob = out + (size_t)(n0 + qt*32)*HIDD + hd*32 + ni*8 + t4*2;
      *(uint2*)(ob + (size_t)r0*HIDD)     = make_uint2(f2tf32(c0*inv0), f2tf32(c1*inv0));
      *(uint2*)(ob + (size_t)(r0+8)*HIDD) = make_uint2(f2tf32(c2*inv1), f2tf32(c3*inv1));
    }
    __syncthreads();
  }
}

// ================= launch =================
extern "C" void kernel_launch(void* const* d_in, const int* in_sizes, int n_in,
                              void* d_out, int out_size) {
  const float* x   = (const float*)d_in[0];
  const float* W0  = (const float*)d_in[1];
  const float* b0  = (const float*)d_in[2];
  const float* Wh  = (const float*)d_in[3];
  const float* bh  = (const float*)d_in[4];
  const float* bng = (const float*)d_in[5];
  const float* bnb = (const float*)d_in[6];
  const float* bnm = (const float*)d_in[7];
  const float* bnv = (const float*)d_in[8];
  const float* aiw = (const float*)d_in[9];
  const float* aib = (const float*)d_in[10];
  const float* aow = (const float*)d_in[11];
  const float* aob = (const float*)d_in[12];
  const int*  eidx = (const int*)d_in[13];

  float* out_final = (float*)d_out;
  float* out_emb   = out_final + (size_t)NN*HIDD;

  const int* src = eidx;
  const int* dst = eidx + NE;

  float *p_h, *p_agg, *p_qkv, *p_attno;
  int* p_count;
  uint32_t* p_wr;
  cudaGetSymbolAddress((void**)&p_h,     g_h);
  cudaGetSymbolAddress((void**)&p_agg,   g_agg);
  cudaGetSymbolAddress((void**)&p_qkv,   g_qkv);
  cudaGetSymbolAddress((void**)&p_attno, g_attno);
  cudaGetSymbolAddress((void**)&p_count, g_count);
  cudaGetSymbolAddress((void**)&p_wr,    g_wr);

  const int GEMM_SMEM = 2*128*68*4;       // 69632
  const int ATTN_SMEM = ATTN_FLOATS*4;    // 226432
  cudaFuncSetAttribute(gemm_mma_kernel<0,1,64,0,1>,  cudaFuncAttributeMaxDynamicSharedMemorySize, GEMM_SMEM);
  cudaFuncSetAttribute(gemm_mma_kernel<0,1,128,0,1>, cudaFuncAttributeMaxDynamicSharedMemorySize, GEMM_SMEM);
  cudaFuncSetAttribute(gemm_mma_kernel<1,0,128,0,1>, cudaFuncAttributeMaxDynamicSharedMemorySize, GEMM_SMEM);
  cudaFuncSetAttribute(gemm_mma_kernel<1,0,128,1,0>, cudaFuncAttributeMaxDynamicSharedMemorySize, GEMM_SMEM);
  cudaFuncSetAttribute(attn_mma_kernel,              cudaFuncAttributeMaxDynamicSharedMemorySize, ATTN_SMEM);

  // weight pre-round (independent of CSR chain)
  roundw_kernel<<<120, 256>>>(W0, Wh, aiw, aow);

  // CSR build
  cudaMemsetAsync(p_count, 0, NN*sizeof(int));
  count_kernel<<<NE/256, 256>>>(dst);
  scan1_kernel<<<256, 256>>>();
  scan2_kernel<<<1, 256>>>();
  scan3_kernel<<<256, 256>>>();
  fill_kernel<<<NE/256, 256>>>(src, dst);

  // layer 0
  agg64_kernel<<<NN*32/256, 256>>>(x, p_agg);
  gemm_mma_kernel<0,1,64,0,1><<<dim3(512,1), 256, GEMM_SMEM>>>(
      p_agg, p_wr, b0, bng, bnb, bnm, bnv, p_h, 128, nullptr);

  // layers 1..3
  for(int l = 0; l < 3; l++){
    agg128_kernel<<<NN*32/256, 256>>>(p_h, p_agg);
    gemm_mma_kernel<0,1,128,0,1><<<dim3(512,1), 256, GEMM_SMEM>>>(
        p_agg, p_wr + 8192 + l*16384, bh + l*HIDD,
        bng + (l+1)*HIDD, bnb + (l+1)*HIDD, bnm + (l+1)*HIDD, bnv + (l+1)*HIDD,
        p_h, 128, nullptr);
  }

  // qkv projection (output rounded for attention)
  gemm_mma_kernel<1,0,128,0,1><<<dim3(512,3), 256, GEMM_SMEM>>>(
      p_h, p_wr + 57344, aib, nullptr, nullptr, nullptr, nullptr, p_qkv, 384, nullptr);

  // attention
  attn_mma_kernel<<<NG*4*2, 256, ATTN_SMEM>>>(p_qkv, p_attno);

  // output projection + fused mean pool (unrounded terminal output)
  cudaMemsetAsync(out_emb, 0, NG*HIDD*sizeof(float));
  gemm_mma_kernel<1,0,128,1,0><<<dim3(512,1), 256, GEMM_SMEM>>>(
      p_attno, p_wr + 106496, aob, nullptr, nullptr, nullptr, nullptr, out_final, 128, out_emb);
}

// round 12
// speedup vs baseline: 3.4768x; 1.0186x over previous
#include <cuda_runtime.h>
#include <cstdint>

#define NN 65536
#define NE (NN*16)
#define NG 128
#define PN 512
#define HIDD 128
#define INDIM 64
#define BN_EPS 1e-5f

__device__ __forceinline__ uint32_t f2tf32(float f){
  uint32_t u; asm("cvt.rna.tf32.f32 %0, %1;" : "=r"(u) : "f"(f)); return u;
}
__device__ __forceinline__ void mma_tf32(float& c0, float& c1, float& c2, float& c3,
                                         uint32_t a0, uint32_t a1, uint32_t a2, uint32_t a3,
                                         uint32_t b0, uint32_t b1){
  asm volatile("mma.sync.aligned.m16n8k8.row.col.f32.tf32.tf32.f32 "
               "{%0,%1,%2,%3}, {%4,%5,%6,%7}, {%8,%9}, {%0,%1,%2,%3};"
               : "+f"(c0), "+f"(c1), "+f"(c2), "+f"(c3)
               : "r"(a0), "r"(a1), "r"(a2), "r"(a3), "r"(b0), "r"(b1));
}
__device__ __forceinline__ uint4 q4(float4 v){
  return make_uint4(f2tf32(v.x), f2tf32(v.y), f2tf32(v.z), f2tf32(v.w));
}
__device__ __forceinline__ void cp16(uint32_t* dst, const uint32_t* src){
  uint32_t d = (uint32_t)__cvta_generic_to_shared(dst);
  asm volatile("cp.async.cg.shared.global [%0], [%1], 16;" :: "r"(d), "l"(src));
}
#define CP_COMMIT() asm volatile("cp.async.commit_group;" ::: "memory")

// ================= scratch =================
__device__ int    g_count[NN];
__device__ int    g_rowptr[NN+1];
__device__ int    g_cursor[NN];
__device__ int    g_part[256];
__device__ int    g_poff[256];
__device__ float2 g_edge[NE];     // (src bits, weight)
__device__ float  g_dis[NN];
__device__ float  g_selfn[NN];
__device__ float  g_h[(size_t)NN*HIDD];
__device__ float  g_agg[(size_t)NN*HIDD];
__device__ float  g_qkv[(size_t)NN*3*HIDD];
__device__ float  g_attno[(size_t)NN*HIDD];
__device__ uint32_t g_wr[122880];   // pre-rounded weights: W0|Wh|aiw|aow

// ================= weight pre-round (tf32) =================
__global__ void roundw_kernel(const float* __restrict__ W0, const float* __restrict__ Wh,
                              const float* __restrict__ aiw, const float* __restrict__ aow){
  int i = (blockIdx.x*256 + threadIdx.x)*4;
  float4 v;
  if(i < 8192)        v = *(const float4*)(W0 + i);
  else if(i < 57344)  v = *(const float4*)(Wh + (i - 8192));
  else if(i < 106496) v = *(const float4*)(aiw + (i - 57344));
  else                v = *(const float4*)(aow + (i - 106496));
  *(uint4*)(g_wr + i) = q4(v);
}

// ================= CSR build =================
__global__ void count_kernel(const int* __restrict__ dst){
  int e = blockIdx.x*blockDim.x + threadIdx.x;
  if(e < NE) atomicAdd(&g_count[dst[e]], 1);
}
__global__ void scan1_kernel(){
  __shared__ int wsum[8];
  int b = blockIdx.x, t = threadIdx.x;
  int i = b*256 + t;
  int c = g_count[i];
  float dis = rsqrtf((float)(c + 1));
  g_dis[i] = dis;
  g_selfn[i] = dis*dis;
  int lane = t & 31, w = t >> 5;
  int v = c;
  #pragma unroll
  for(int o=1;o<32;o<<=1){ int u=__shfl_up_sync(0xffffffffu,v,o); if(lane>=o) v+=u; }
  if(lane==31) wsum[w]=v;
  __syncthreads();
  if(w==0){
    int s = (lane<8)? wsum[lane] : 0;
    #pragma unroll
    for(int o=1;o<8;o<<=1){ int u=__shfl_up_sync(0xffffffffu,s,o); if(lane>=o) s+=u; }
    if(lane<8) wsum[lane]=s;
  }
  __syncthreads();
  int excl = v - c + (w ? wsum[w-1] : 0);
  g_rowptr[i] = excl;
  if(t==255) g_part[b] = excl + c;
}
__global__ void scan2_kernel(){
  __shared__ int wsum[8];
  int t = threadIdx.x;
  int v = g_part[t];
  int lane = t & 31, w = t >> 5;
  int s = v;
  #pragma unroll
  for(int o=1;o<32;o<<=1){ int u=__shfl_up_sync(0xffffffffu,s,o); if(lane>=o) s+=u; }
  if(lane==31) wsum[w]=s;
  __syncthreads();
  if(w==0){
    int x = (lane<8)? wsum[lane] : 0;
    #pragma unroll
    for(int o=1;o<8;o<<=1){ int u=__shfl_up_sync(0xffffffffu,x,o); if(lane>=o) x+=u; }
    if(lane<8) wsum[lane]=x;
  }
  __syncthreads();
  g_poff[t] = s - v + (w ? wsum[w-1] : 0);
}
__global__ void scan3_kernel(){
  int b = blockIdx.x, t = threadIdx.x;
  int i = b*256 + t;
  int r = g_rowptr[i] + g_poff[b];
  g_rowptr[i] = r;
  g_cursor[i] = r;
  if(i == 0) g_rowptr[NN] = NE;
}
__global__ void fill_kernel(const int* __restrict__ src, const int* __restrict__ dst){
  int e = blockIdx.x*blockDim.x + threadIdx.x;
  if(e >= NE) return;
  int s = src[e], d = dst[e];
  int pos = atomicAdd(&g_cursor[d], 1);
  g_edge[pos] = make_float2(__int_as_float(s), g_dis[s]*g_dis[d]);
}

// ======== aggregation (warp/node; edge prefetch + shfl bcast; tf32-rounded output) ========
__global__ void agg64_kernel(const float* __restrict__ hin, float* __restrict__ out){
  int gw = (blockIdx.x*blockDim.x + threadIdx.x) >> 5;
  int lane = threadIdx.x & 31;
  if(gw >= NN) return;
  float2 a = *((const float2*)(hin + (size_t)gw*INDIM) + lane);
  float sn = g_selfn[gw];
  a.x *= sn; a.y *= sn;
  int beg = g_rowptr[gw], end = g_rowptr[gw+1];
  for(int b = beg; b < end; b += 32){
    int m = min(32, end - b);
    float2 myed = make_float2(0.f, 0.f);
    if(lane < m) myed = g_edge[b + lane];
    #pragma unroll 2
    for(int i = 0; i < m; i++){
      int   s = __shfl_sync(0xffffffffu, __float_as_int(myed.x), i);
      float w = __shfl_sync(0xffffffffu, myed.y, i);
      float2 v = *((const float2*)(hin + (size_t)s*INDIM) + lane);
      a.x += w*v.x; a.y += w*v.y;
    }
  }
  *((uint2*)(out + (size_t)gw*INDIM) + lane) = make_uint2(f2tf32(a.x), f2tf32(a.y));
}
__global__ void agg128_kernel(const float* __restrict__ hin, float* __restrict__ out){
  int gw = (blockIdx.x*blockDim.x + threadIdx.x) >> 5;
  int lane = threadIdx.x & 31;
  if(gw >= NN) return;
  float4 a = *((const float4*)(hin + (size_t)gw*HIDD) + lane);
  float sn = g_selfn[gw];
  a.x *= sn; a.y *= sn; a.z *= sn; a.w *= sn;
  int beg = g_rowptr[gw], end = g_rowptr[gw+1];
  for(int b = beg; b < end; b += 32){
    int m = min(32, end - b);
    float2 myed = make_float2(0.f, 0.f);
    if(lane < m) myed = g_edge[b + lane];
    #pragma unroll 2
    for(int i = 0; i < m; i++){
      int   s = __shfl_sync(0xffffffffu, __float_as_int(myed.x), i);
      float w = __shfl_sync(0xffffffffu, myed.y, i);
      float4 v = *((const float4*)(hin + (size_t)s*HIDD) + lane);
      a.x += w*v.x; a.y += w*v.y; a.z += w*v.z; a.w += w*v.w;
    }
  }
  *((uint4*)(out + (size_t)gw*HIDD) + lane) = q4(a);
}

// ========== tf32 mma.sync GEMM: cp.async double-buffered, CK=32, 2 CTAs/SM ==========
// A, B point to pre-rounded tf32 bits. RND=1: round outputs. POOL=1: fused mean pool.
template<int BT, int EPI, int KK, int POOL, int RND>
__global__ __launch_bounds__(256, 2)
void gemm_mma_kernel(const float* __restrict__ A, const uint32_t* __restrict__ B,
                     const float* __restrict__ bias,
                     const float* __restrict__ bng, const float* __restrict__ bnb,
                     const float* __restrict__ bnm, const float* __restrict__ bnv,
                     float* __restrict__ C, int Ndt, float* __restrict__ emb)
{
  constexpr int CK  = 32;
  constexpr int NCH = KK / CK;
  constexpr int SA  = 36;          // A (and BT1 B) row stride in u32
  constexpr int SBN = 132;         // BT0 B row stride
  constexpr int BUFA = 128*SA;     // 4608 u32
  constexpr int BUF  = 2*BUFA;     // 9216 u32 per stage buffer (A + B)
  extern __shared__ uint32_t sm[];
  const int tid = threadIdx.x;
  const int lane = tid & 31, wid = tid >> 5;
  const int row0 = blockIdx.x * 128;
  const int col0 = blockIdx.y * 128;
  const uint32_t* Ag = (const uint32_t*)A;

  const int m0 = (wid >> 1) * 32;
  const int n0 = (wid & 1) * 64;
  const int g  = lane >> 2;
  const int t4 = lane & 3;

  float acc[2][8][4];
  #pragma unroll
  for(int i=0;i<2;i++)
    #pragma unroll
    for(int j=0;j<8;j++)
      #pragma unroll
      for(int q=0;q<4;q++) acc[i][j][q]=0.f;

  // ---- async stage of one CK-chunk into buffer (ch&1) ----
  auto stage = [&](int ch){
    const int kbase = ch*CK;
    uint32_t* As = sm + (ch & 1)*BUF;
    uint32_t* Bs = As + BUFA;
    #pragma unroll
    for(int i = 0; i < 4; i++){
      int idx = tid + i*256;
      int r = idx >> 3, q = idx & 7;
      cp16(As + r*SA + q*4, Ag + (size_t)(row0 + r)*KK + kbase + q*4);
    }
    if(BT){
      #pragma unroll
      for(int i = 0; i < 4; i++){
        int idx = tid + i*256;
        int r = idx >> 3, q = idx & 7;
        cp16(Bs + r*SA + q*4, B + (size_t)(col0 + r)*KK + kbase + q*4);
      }
    } else {
      #pragma unroll
      for(int i = 0; i < 4; i++){
        int idx = tid + i*256;
        int k = idx >> 5, n4 = idx & 31;
        cp16(Bs + k*SBN + n4*4, B + (size_t)(kbase + k)*Ndt + col0 + n4*4);
      }
    }
    CP_COMMIT();
  };

  stage(0);

  #pragma unroll 1
  for(int ch = 0; ch < NCH; ch++){
    if(ch + 1 < NCH) stage(ch + 1);
    if(ch + 1 < NCH) asm volatile("cp.async.wait_group 1;" ::: "memory");
    else             asm volatile("cp.async.wait_group 0;" ::: "memory");
    __syncthreads();

    uint32_t* As = sm + (ch & 1)*BUF;
    uint32_t* Bs = As + BUFA;
    const uint32_t* Aw0 = As + (m0 + g)*SA + t4;
    const uint32_t* Aw1 = As + (m0 + 16 + g)*SA + t4;
    const uint32_t* Bw1 = Bs + (n0 + g)*SA + t4;
    const uint32_t* Bw0 = Bs + t4*SBN + n0 + g;

    #pragma unroll 1
    for(int ks = 0; ks < CK/8; ks++){
      const int k0 = ks*8;
      uint32_t af[2][4];
      af[0][0] = Aw0[k0];       af[0][1] = Aw0[8*SA + k0];
      af[0][2] = Aw0[k0 + 4];   af[0][3] = Aw0[8*SA + k0 + 4];
      af[1][0] = Aw1[k0];       af[1][1] = Aw1[8*SA + k0];
      af[1][2] = Aw1[k0 + 4];   af[1][3] = Aw1[8*SA + k0 + 4];
      #pragma unroll
      for(int nj = 0; nj < 8; nj++){
        uint32_t b0, b1;
        if(BT){
          b0 = Bw1[nj*8*SA + k0];
          b1 = Bw1[nj*8*SA + k0 + 4];
        } else {
          b0 = Bw0[k0*SBN + nj*8];
          b1 = Bw0[(k0+4)*SBN + nj*8];
        }
        mma_tf32(acc[0][nj][0], acc[0][nj][1], acc[0][nj][2], acc[0][nj][3],
                 af[0][0], af[0][1], af[0][2], af[0][3], b0, b1);
        mma_tf32(acc[1][nj][0], acc[1][nj][1], acc[1][nj][2], acc[1][nj][3],
                 af[1][0], af[1][1], af[1][2], af[1][3], b0, b1);
      }
    }
    if(ch + 1 < NCH) __syncthreads();   // protect buffer (ch&1) before chunk ch+2 staging
  }

  float cs[8][2];
  if(POOL){
    #pragma unroll
    for(int nj=0;nj<8;nj++){ cs[nj][0]=0.f; cs[nj][1]=0.f; }
  }

  #pragma unroll
  for(int mi = 0; mi < 2; mi++){
    #pragma unroll
    for(int nj = 0; nj < 8; nj++){
      int c = col0 + n0 + nj*8 + t4*2;
      float s0, s1;
      if(EPI){
        s0 = bng[c  ]*rsqrtf(bnv[c  ] + BN_EPS);
        s1 = bng[c+1]*rsqrtf(bnv[c+1] + BN_EPS);
      }
      #pragma unroll
      for(int h = 0; h < 2; h++){
        int r = row0 + m0 + mi*16 + g + h*8;
        float v0 = acc[mi][nj][h*2+0] + bias[c];
        float v1 = acc[mi][nj][h*2+1] + bias[c+1];
        if(EPI){
          v0 = fmaxf((v0 - bnm[c  ])*s0 + bnb[c  ], 0.f);
          v1 = fmaxf((v1 - bnm[c+1])*s1 + bnb[c+1], 0.f);
        }
        if(POOL){ cs[nj][0] += v0; cs[nj][1] += v1; }
        if(RND){
          *(uint2*)(C + (size_t)r*Ndt + c) = make_uint2(f2tf32(v0), f2tf32(v1));
        } else {
          *(float2*)(C + (size_t)r*Ndt + c) = make_float2(v0, v1);
        }
      }
    }
  }

  if(POOL){
    int graph = row0 >> 9;
    #pragma unroll
    for(int nj = 0; nj < 8; nj++){
      float s0 = cs[nj][0], s1 = cs[nj][1];
      #pragma unroll
      for(int o = 4; o <= 16; o <<= 1){
        s0 += __shfl_xor_sync(0xffffffffu, s0, o);
        s1 += __shfl_xor_sync(0xffffffffu, s1, o);
      }
      if(g == 0){
        int c = col0 + n0 + nj*8 + t4*2;
        atomicAdd(&emb[graph*HIDD + c],   s0*(1.0f/PN));
        atomicAdd(&emb[graph*HIDD + c+1], s1*(1.0f/PN));
      }
    }
  }
}

// ================= attention via tf32 mma: CTA per (graph, head, half) ===========
// qkv is pre-rounded tf32 bits -> staging is pure copy; 1/sqrt(32) folded into exp.
#define KSTR 36
#define VSTR 40
#define SSTR 516
#define QSTR 36
#define KS_OFF 0
#define VS_OFF (512*KSTR)
#define S_OFF  (VS_OFF + 512*VSTR)
#define Q_OFF  (S_OFF + 32*SSTR)
#define SINV_OFF (Q_OFF + 32*QSTR)
#define ATTN_FLOATS (SINV_OFF + 32)

__global__ __launch_bounds__(256)
void attn_mma_kernel(const float* __restrict__ qkv, float* __restrict__ out){
  extern __shared__ float smf[];
  float* S    = smf + S_OFF;
  float* Sinv = smf + SINV_OFF;
  uint32_t* Ku = (uint32_t*)(smf + KS_OFF);
  uint32_t* Vu = (uint32_t*)(smf + VS_OFF);
  uint32_t* Su = (uint32_t*)S;
  uint32_t* Qu = (uint32_t*)(smf + Q_OFF);

  int g    = blockIdx.x >> 3;
  int hd   = (blockIdx.x >> 1) & 3;
  int half = blockIdx.x & 1;
  int n0 = g*PN;
  int t = threadIdx.x;
  int lane = t & 31, warp = t >> 5;
  int gq = lane >> 2, t4 = lane & 3;
  const float scale = 0.17677669529663687f;   // 1/sqrt(32), folded into exp

  for(int idx = t; idx < PN*8; idx += 256){
    int r = idx >> 3, d4 = (idx & 7)*4;
    const uint32_t* row = (const uint32_t*)qkv + (size_t)(n0 + r)*384 + hd*32;
    *(uint4*)(Ku + r*KSTR + d4) = *(const uint4*)(row + 128 + d4);
    *(uint4*)(Vu + r*VSTR + d4) = *(const uint4*)(row + 256 + d4);
  }
  __syncthreads();

  for(int qi8 = 0; qi8 < 8; qi8++){
    int qt = half*8 + qi8;
    for(int idx = t; idx < 32*8; idx += 256){
      int r = idx >> 3, d4 = (idx & 7)*4;
      *(uint4*)(Qu + r*QSTR + d4) =
        *(const uint4*)((const uint32_t*)qkv + (size_t)(n0 + qt*32 + r)*384 + hd*32 + d4);
    }
    __syncthreads();

    // Phase A: S = Q K^T (unscaled)
    {
      float c[2][8][4];
      #pragma unroll
      for(int i=0;i<2;i++)
        #pragma unroll
        for(int j=0;j<8;j++)
          #pragma unroll
          for(int q=0;q<4;q++) c[i][j][q]=0.f;

      #pragma unroll 1
      for(int ks = 0; ks < 4; ks++){
        int k0 = ks*8;
        uint32_t a[2][4];
        #pragma unroll
        for(int mi=0;mi<2;mi++){
          const uint32_t* qb = Qu + (mi*16+gq)*QSTR + k0 + t4;
          a[mi][0]=qb[0]; a[mi][1]=qb[8*QSTR]; a[mi][2]=qb[4]; a[mi][3]=qb[8*QSTR+4];
        }
        #pragma unroll
        for(int nj=0;nj<8;nj++){
          const uint32_t* kb = Ku + (warp*64+nj*8+gq)*KSTR + k0 + t4;
          uint32_t b0 = kb[0], b1 = kb[4];
          mma_tf32(c[0][nj][0],c[0][nj][1],c[0][nj][2],c[0][nj][3],
                   a[0][0],a[0][1],a[0][2],a[0][3], b0,b1);
          mma_tf32(c[1][nj][0],c[1][nj][1],c[1][nj][2],c[1][nj][3],
                   a[1][0],a[1][1],a[1][2],a[1][3], b0,b1);
        }
      }
      #pragma unroll
      for(int mi=0;mi<2;mi++)
        #pragma unroll
        for(int nj=0;nj<8;nj++){
          float* sp = S + (mi*16+gq)*SSTR + warp*64 + nj*8 + t4*2;
          *(float2*)(sp)          = make_float2(c[mi][nj][0], c[mi][nj][1]);
          *(float2*)(sp + 8*SSTR) = make_float2(c[mi][nj][2], c[mi][nj][3]);
        }
    }
    __syncthreads();

    // Phase B: exp(s*scale) + sum (float4); normalization deferred
    for(int rr = 0; rr < 4; rr++){
      int r = warp*4 + rr;
      float sum = 0.f;
      float* Srow = S + r*SSTR;
      #pragma unroll
      for(int jj = 0; jj < 4; jj++){
        int j4 = (jj*32 + lane)*4;
        float4 v = *(float4*)(Srow + j4);
        v.x = __expf(v.x*scale); v.y = __expf(v.y*scale);
        v.z = __expf(v.z*scale); v.w = __expf(v.w*scale);
        sum += v.x + v.y + v.z + v.w;
        *(uint4*)((uint32_t*)Srow + j4) = q4(v);
      }
      #pragma unroll
      for(int o=16;o;o>>=1) sum += __shfl_xor_sync(0xffffffffu, sum, o);
      if(lane == 0) Sinv[r] = 1.f/sum;
    }
    __syncthreads();

    // Phase C: O = (E V) * Sinv; output rounded (feeds final GEMM)
    {
      int mi = warp & 1, ni = warp >> 1;
      float c0=0.f,c1=0.f,c2=0.f,c3=0.f;
      const uint32_t* pbase = Su + (mi*16+gq)*SSTR + t4;
      const uint32_t* vbase = Vu + t4*VSTR + ni*8 + gq;
      #pragma unroll 4
      for(int ks = 0; ks < 64; ks++){
        int k0 = ks*8;
        uint32_t a0 = pbase[k0], a1 = pbase[8*SSTR + k0];
        uint32_t a2 = pbase[k0+4], a3 = pbase[8*SSTR + k0+4];
        uint32_t b0 = vbase[k0*VSTR], b1 = vbase[(k0+4)*VSTR];
        mma_tf32(c0,c1,c2,c3, a0,a1,a2,a3, b0,b1);
      }
      int r0 = mi*16 + gq;
      float inv0 = Sinv[r0], inv1 = Sinv[r0+8];
      float* ob = out + (size_t)(n0 + qt*32)*HIDD + hd*32 + ni*8 + t4*2;
      *(uint2*)(ob + (size_t)r0*HIDD)     = make_uint2(f2tf32(c0*inv0), f2tf32(c1*inv0));
      *(uint2*)(ob + (size_t)(r0+8)*HIDD) = make_uint2(f2tf32(c2*inv1), f2tf32(c3*inv1));
    }
    __syncthreads();
  }
}

// ================= launch =================
extern "C" void kernel_launch(void* const* d_in, const int* in_sizes, int n_in,
                              void* d_out, int out_size) {
  const float* x   = (const float*)d_in[0];
  const float* W0  = (const float*)d_in[1];
  const float* b0  = (const float*)d_in[2];
  const float* Wh  = (const float*)d_in[3];
  const float* bh  = (const float*)d_in[4];
  const float* bng = (const float*)d_in[5];
  const float* bnb = (const float*)d_in[6];
  const float* bnm = (const float*)d_in[7];
  const float* bnv = (const float*)d_in[8];
  const float* aiw = (const float*)d_in[9];
  const float* aib = (const float*)d_in[10];
  const float* aow = (const float*)d_in[11];
  const float* aob = (const float*)d_in[12];
  const int*  eidx = (const int*)d_in[13];

  float* out_final = (float*)d_out;
  float* out_emb   = out_final + (size_t)NN*HIDD;

  const int* src = eidx;
  const int* dst = eidx + NE;

  float *p_h, *p_agg, *p_qkv, *p_attno;
  int* p_count;
  uint32_t* p_wr;
  cudaGetSymbolAddress((void**)&p_h,     g_h);
  cudaGetSymbolAddress((void**)&p_agg,   g_agg);
  cudaGetSymbolAddress((void**)&p_qkv,   g_qkv);
  cudaGetSymbolAddress((void**)&p_attno, g_attno);
  cudaGetSymbolAddress((void**)&p_count, g_count);
  cudaGetSymbolAddress((void**)&p_wr,    g_wr);

  const int GEMM_SMEM = 2*9216*4;         // 73728: 2 stage buffers
  const int ATTN_SMEM = ATTN_FLOATS*4;    // 226432
  cudaFuncSetAttribute(gemm_mma_kernel<0,1,64,0,1>,  cudaFuncAttributeMaxDynamicSharedMemorySize, GEMM_SMEM);
  cudaFuncSetAttribute(gemm_mma_kernel<0,1,128,0,1>, cudaFuncAttributeMaxDynamicSharedMemorySize, GEMM_SMEM);
  cudaFuncSetAttribute(gemm_mma_kernel<1,0,128,0,1>, cudaFuncAttributeMaxDynamicSharedMemorySize, GEMM_SMEM);
  cudaFuncSetAttribute(gemm_mma_kernel<1,0,128,1,0>, cudaFuncAttributeMaxDynamicSharedMemorySize, GEMM_SMEM);
  cudaFuncSetAttribute(attn_mma_kernel,              cudaFuncAttributeMaxDynamicSharedMemorySize, ATTN_SMEM);

  // weight pre-round (independent of CSR chain)
  roundw_kernel<<<120, 256>>>(W0, Wh, aiw, aow);

  // CSR build
  cudaMemsetAsync(p_count, 0, NN*sizeof(int));
  count_kernel<<<NE/256, 256>>>(dst);
  scan1_kernel<<<256, 256>>>();
  scan2_kernel<<<1, 256>>>();
  scan3_kernel<<<256, 256>>>();
  fill_kernel<<<NE/256, 256>>>(src, dst);

  // layer 0
  agg64_kernel<<<NN*32/256, 256>>>(x, p_agg);
  gemm_mma_kernel<0,1,64,0,1><<<dim3(512,1), 256, GEMM_SMEM>>>(
      p_agg, p_wr, b0, bng, bnb, bnm, bnv, p_h, 128, nullptr);

  // layers 1..3
  for(int l = 0; l < 3; l++){
    agg128_kernel<<<NN*32/256, 256>>>(p_h, p_agg);
    gemm_mma_kernel<0,1,128,0,1><<<dim3(512,1), 256, GEMM_SMEM>>>(
        p_agg, p_wr + 8192 + l*16384, bh + l*HIDD,
        bng + (l+1)*HIDD, bnb + (l+1)*HIDD, bnm + (l+1)*HIDD, bnv + (l+1)*HIDD,
        p_h, 128, nullptr);
  }

  // qkv projection (output rounded for attention)
  gemm_mma_kernel<1,0,128,0,1><<<dim3(512,3), 256, GEMM_SMEM>>>(
      p_h, p_wr + 57344, aib, nullptr, nullptr, nullptr, nullptr, p_qkv, 384, nullptr);

  // attention
  attn_mma_kernel<<<NG*4*2, 256, ATTN_SMEM>>>(p_qkv, p_attno);

  // output projection + fused mean pool (unrounded terminal output)
  cudaMemsetAsync(out_emb, 0, NG*HIDD*sizeof(float));
  gemm_mma_kernel<1,0,128,1,0><<<dim3(512,1), 256, GEMM_SMEM>>>(
      p_attno, p_wr + 106496, aob, nullptr, nullptr, nullptr, nullptr, out_final, 128, out_emb);
}